// round 6
// baseline (speedup 1.0000x reference)
#include <cuda_runtime.h>
#include <math.h>

#define HH  16
#define SS  2048
#define DD  1024
#define DHD 64
#define HID 4096

// ---------------- scratch ----------------------------------------------------
__device__ float g_q   [HH * SS * DHD];
__device__ float g_qc  [HH * SS * DHD];
__device__ float g_kc  [HH * SS * DHD];
__device__ float g_tmp [SS * DD];
__device__ float g_y1  [SS * DD];
__device__ float g_y2  [SS * DD];
__device__ float g_hid [SS * HID];

// ---------------- helpers ----------------------------------------------------
__device__ __forceinline__ void mma_tf32(
    float& d0, float& d1, float& d2, float& d3,
    unsigned a0, unsigned a1, unsigned a2, unsigned a3,
    unsigned b0, unsigned b1)
{
    asm volatile(
        "mma.sync.aligned.m16n8k8.row.col.f32.tf32.tf32.f32 "
        "{%0,%1,%2,%3}, {%4,%5,%6,%7}, {%8,%9}, {%0,%1,%2,%3};"
        : "+f"(d0), "+f"(d1), "+f"(d2), "+f"(d3)
        : "r"(a0), "r"(a1), "r"(a2), "r"(a3), "r"(b0), "r"(b1));
}
__device__ __forceinline__ void cp16(float* dst, const float* src) {
    unsigned d = (unsigned)__cvta_generic_to_shared(dst);
    asm volatile("cp.async.cg.shared.global [%0], [%1], 16;" :: "r"(d), "l"(src));
}
#define CP_COMMIT() asm volatile("cp.async.commit_group;")
#define CP_WAIT0()  asm volatile("cp.async.wait_group 0;")
#define CP_WAIT1()  asm volatile("cp.async.wait_group 1;")

// round-to-nearest tf32 (on a float already in a register)
__device__ __forceinline__ unsigned tfr(float f) {
    unsigned u; asm("cvt.rna.tf32.f32 %0, %1;" : "=r"(u) : "f"(f)); return u;
}
// ldmatrix x4 (tf32-as-b16 trick: one 8x4-float row == one 16B ldmatrix row)
__device__ __forceinline__ void ldsm4(unsigned& r0, unsigned& r1,
                                      unsigned& r2, unsigned& r3, const float* p)
{
    unsigned a = (unsigned)__cvta_generic_to_shared(p);
    asm volatile("ldmatrix.sync.aligned.m8n8.x4.shared.b16 {%0,%1,%2,%3}, [%4];"
                 : "=r"(r0), "=r"(r1), "=r"(r2), "=r"(r3) : "r"(a));
}

// ======================= 3-stage cp.async GEMM ==============================
#define BM 128
#define BK 32
#define SA 36

template<int BN>
__global__ __launch_bounds__(256)
void mma_gemm(const float* __restrict__ A, const float* __restrict__ B,
              const float* __restrict__ bias, float* __restrict__ C,
              int K, int lda, int ldb, int ldc,
              long long sA, long long sB, long long sBias, long long sC,
              float alpha, int relu)
{
    constexpr int SBNT  = BN + 8;
    constexpr int NT    = BN / 16;
    constexpr int BITER = (BK * BN / 4) / 256;
    constexpr int KSTEP = 256 / (BN / 4);
    constexpr int ABUF  = BM * SA;
    constexpr int BBUF  = BK * SBNT;

    extern __shared__ float sm[];
    float* As = sm;               // 3 * ABUF
    float* Bs = sm + 3 * ABUF;    // 3 * BBUF

    const int batch = blockIdx.z;
    A += (long long)batch * sA;
    B += (long long)batch * sB;
    C += (long long)batch * sC;
    const float* biasp = bias ? bias + (long long)batch * sBias : nullptr;

    const int rowStart = blockIdx.y * BM;
    const int colStart = blockIdx.x * BN;
    const int nK = K / BK;

    const int tid  = threadIdx.x;
    const int wid  = tid >> 5, lane = tid & 31;
    const int g    = lane >> 2, tig = lane & 3;
    const int warpM = wid & 3, warpN = wid >> 2;

    const int a_m = tid >> 3, a_k = (tid & 7) << 2;
    const float* Agp = A + (long long)(rowStart + a_m) * lda + a_k;

    const int b_r = tid / (BN / 4), b_c = (tid % (BN / 4)) << 2;
    const float* Bgp = B + (long long)b_r * ldb + colStart + b_c;

    // ldmatrix lane address offsets for A fragments
    const int lm_row = lane & 15;
    const int lm_col = (lane & 16) ? 4 : 0;

    auto issue = [&](int kt) {
        const int k0 = kt * BK;
        float* Ad = As + (kt % 3) * ABUF;
        float* Bd = Bs + (kt % 3) * BBUF;
#pragma unroll
        for (int i = 0; i < 4; i++)
            cp16(Ad + (a_m + 32 * i) * SA + a_k, Agp + (long long)(32 * i) * lda + k0);
#pragma unroll
        for (int i = 0; i < BITER; i++)
            cp16(Bd + (b_r + KSTEP * i) * SBNT + b_c,
                 Bgp + (long long)(KSTEP * i + k0) * ldb);
        CP_COMMIT();
    };

    float acc[2][NT][4];
#pragma unroll
    for (int mt = 0; mt < 2; mt++)
#pragma unroll
        for (int nt = 0; nt < NT; nt++)
#pragma unroll
            for (int i = 0; i < 4; i++) acc[mt][nt][i] = 0.f;

    issue(0);
    if (nK > 1) issue(1);

    for (int kt = 0; kt < nK; kt++) {
        CP_WAIT1();
        __syncthreads();                    // tile kt visible to all warps
        if (kt + 2 < nK) issue(kt + 2);

        const float* Ac = As + (kt % 3) * ABUF;
        const float* Bc = Bs + (kt % 3) * BBUF;
#pragma unroll
        for (int ks = 0; ks < 4; ks++) {
            const int kb = ks * 8;
            unsigned af[2][4];
#pragma unroll
            for (int mt = 0; mt < 2; mt++) {
                const int mr = warpM * 32 + mt * 16;
                unsigned r0, r1, r2, r3;
                ldsm4(r0, r1, r2, r3, &Ac[(mr + lm_row) * SA + kb + lm_col]);
                af[mt][0] = tfr(__uint_as_float(r0));
                af[mt][1] = tfr(__uint_as_float(r1));
                af[mt][2] = tfr(__uint_as_float(r2));
                af[mt][3] = tfr(__uint_as_float(r3));
            }
            unsigned bf[NT][2];
#pragma unroll
            for (int nt = 0; nt < NT; nt++) {
                const int nb = warpN * (BN / 2) + nt * 8;
                bf[nt][0] = tfr(Bc[(kb + tig)     * SBNT + nb + g]);
                bf[nt][1] = tfr(Bc[(kb + tig + 4) * SBNT + nb + g]);
            }
#pragma unroll
            for (int mt = 0; mt < 2; mt++)
#pragma unroll
                for (int nt = 0; nt < NT; nt++)
                    mma_tf32(acc[mt][nt][0], acc[mt][nt][1], acc[mt][nt][2], acc[mt][nt][3],
                             af[mt][0], af[mt][1], af[mt][2], af[mt][3],
                             bf[nt][0], bf[nt][1]);
        }
    }

#pragma unroll
    for (int mt = 0; mt < 2; mt++) {
        const int r = rowStart + warpM * 32 + mt * 16 + g;
#pragma unroll
        for (int nt = 0; nt < NT; nt++) {
            const int cc = colStart + warpN * (BN / 2) + nt * 8 + 2 * tig;
            const float bb0 = biasp ? biasp[cc]     : 0.f;
            const float bb1 = biasp ? biasp[cc + 1] : 0.f;
            float v0 = acc[mt][nt][0] * alpha + bb0;
            float v1 = acc[mt][nt][1] * alpha + bb1;
            float v2 = acc[mt][nt][2] * alpha + bb0;
            float v3 = acc[mt][nt][3] * alpha + bb1;
            if (relu) { v0 = fmaxf(v0, 0.f); v1 = fmaxf(v1, 0.f);
                        v2 = fmaxf(v2, 0.f); v3 = fmaxf(v3, 0.f); }
            *(float2*)&C[(long long)r       * ldc + cc] = make_float2(v0, v1);
            *(float2*)&C[(long long)(r + 8) * ldc + cc] = make_float2(v2, v3);
        }
    }
}

// ======================= fused flash attention ==============================
#define FST 68

template<bool CAUSAL>
__global__ __launch_bounds__(256)
void flash_kernel(const float* __restrict__ Q, const float* __restrict__ KV,
                  float* __restrict__ O)
{
    extern __shared__ float sm[];
    float* Ks = sm;                  // 2 * 64 * FST
    float* Ps = sm + 2 * 64 * FST;   // 128 * FST

    const int h = blockIdx.y;
    const int rowBlk = CAUSAL ? (gridDim.x - 1 - blockIdx.x) : blockIdx.x;
    const float* Qh = Q  + (long long)h * SS * DHD + (long long)rowBlk * 128 * DHD;
    const float* Kh = KV + (long long)h * SS * DHD;

    const int tid = threadIdx.x, wid = tid >> 5, lane = tid & 31;
    const int g = lane >> 2, tig = lane & 3;
    const int mr = wid * 16;

    const int k_r = tid >> 2, k_c = (tid & 3) << 4;

    auto issueK = [&](int t) {
        float* Kd = Ks + (t & 1) * 64 * FST;
        const float* src = Kh + (long long)(t * 64 + k_r) * DHD + k_c;
#pragma unroll
        for (int i = 0; i < 4; i++)
            cp16(Kd + k_r * FST + k_c + 4 * i, src + 4 * i);
        CP_COMMIT();
    };

    // stage Q through Ps, pull rounded fragments into registers
    for (int i = tid; i < 128 * 16; i += 256) {
        int r = i >> 4, c4 = (i & 15) << 2;
        *(float4*)&Ps[r * FST + c4] = *(const float4*)(Qh + r * DHD + c4);
    }
    issueK(0);
    __syncthreads();
    unsigned qf[8][4];
#pragma unroll
    for (int kb = 0; kb < 8; kb++) {
        qf[kb][0] = tfr(Ps[(mr + g)     * FST + kb * 8 + tig]);
        qf[kb][1] = tfr(Ps[(mr + g + 8) * FST + kb * 8 + tig]);
        qf[kb][2] = tfr(Ps[(mr + g)     * FST + kb * 8 + tig + 4]);
        qf[kb][3] = tfr(Ps[(mr + g + 8) * FST + kb * 8 + tig + 4]);
    }

    float o[8][4];
#pragma unroll
    for (int nt = 0; nt < 8; nt++)
#pragma unroll
        for (int i = 0; i < 4; i++) o[nt][i] = 0.f;
    float m0 = -1e30f, m1 = -1e30f, l0 = 0.f, l1 = 0.f;

    const int nTiles = CAUSAL ? 2 * (rowBlk + 1) : SS / 64;
    const int r0 = rowBlk * 128 + mr + g;
    const int r1 = r0 + 8;

    // ldmatrix lane addressing for K fragments (pairs of n8 tiles)
    const int kl_row = (lane & 7) + ((lane & 16) ? 8 : 0);
    const int kl_col = (lane & 8) ? 4 : 0;

    for (int t = 0; t < nTiles; t++) {
        CP_WAIT0();
        __syncthreads();
        if (t + 1 < nTiles) issueK(t + 1);
        const float* Kc = Ks + (t & 1) * 64 * FST;

        // S = Q K^T
        float s[8][4];
#pragma unroll
        for (int nt = 0; nt < 8; nt++) { s[nt][0] = s[nt][1] = s[nt][2] = s[nt][3] = 0.f; }
#pragma unroll
        for (int kb = 0; kb < 8; kb++) {
#pragma unroll
            for (int ntp = 0; ntp < 4; ntp++) {
                unsigned r0u, r1u, r2u, r3u;
                ldsm4(r0u, r1u, r2u, r3u,
                      &Kc[(ntp * 16 + kl_row) * FST + kb * 8 + kl_col]);
                unsigned b00 = tfr(__uint_as_float(r0u));
                unsigned b01 = tfr(__uint_as_float(r1u));
                unsigned b10 = tfr(__uint_as_float(r2u));
                unsigned b11 = tfr(__uint_as_float(r3u));
                mma_tf32(s[2*ntp][0], s[2*ntp][1], s[2*ntp][2], s[2*ntp][3],
                         qf[kb][0], qf[kb][1], qf[kb][2], qf[kb][3], b00, b01);
                mma_tf32(s[2*ntp+1][0], s[2*ntp+1][1], s[2*ntp+1][2], s[2*ntp+1][3],
                         qf[kb][0], qf[kb][1], qf[kb][2], qf[kb][3], b10, b11);
            }
        }

        // scale + mask + online softmax
        const int cb = t * 64;
        float tm0 = -1e30f, tm1 = -1e30f;
#pragma unroll
        for (int nt = 0; nt < 8; nt++) {
            const int c0 = cb + nt * 8 + 2 * tig, c1 = c0 + 1;
            s[nt][0] *= 0.125f; s[nt][1] *= 0.125f;
            s[nt][2] *= 0.125f; s[nt][3] *= 0.125f;
            if (CAUSAL) {
                if (c0 > r0) s[nt][0] = -1e30f;
                if (c1 > r0) s[nt][1] = -1e30f;
                if (c0 > r1) s[nt][2] = -1e30f;
                if (c1 > r1) s[nt][3] = -1e30f;
            }
            tm0 = fmaxf(tm0, fmaxf(s[nt][0], s[nt][1]));
            tm1 = fmaxf(tm1, fmaxf(s[nt][2], s[nt][3]));
        }
        tm0 = fmaxf(tm0, __shfl_xor_sync(0xffffffffu, tm0, 1));
        tm0 = fmaxf(tm0, __shfl_xor_sync(0xffffffffu, tm0, 2));
        tm1 = fmaxf(tm1, __shfl_xor_sync(0xffffffffu, tm1, 1));
        tm1 = fmaxf(tm1, __shfl_xor_sync(0xffffffffu, tm1, 2));

        const float mn0 = fmaxf(m0, tm0), mn1 = fmaxf(m1, tm1);
        const float corr0 = __expf(m0 - mn0), corr1 = __expf(m1 - mn1);
        m0 = mn0; m1 = mn1;

        float rs0 = 0.f, rs1 = 0.f;
#pragma unroll
        for (int nt = 0; nt < 8; nt++) {
            s[nt][0] = __expf(s[nt][0] - mn0); rs0 += s[nt][0];
            s[nt][1] = __expf(s[nt][1] - mn0); rs0 += s[nt][1];
            s[nt][2] = __expf(s[nt][2] - mn1); rs1 += s[nt][2];
            s[nt][3] = __expf(s[nt][3] - mn1); rs1 += s[nt][3];
            *(float2*)&Ps[(mr + g)     * FST + nt * 8 + 2 * tig] = make_float2(s[nt][0], s[nt][1]);
            *(float2*)&Ps[(mr + g + 8) * FST + nt * 8 + 2 * tig] = make_float2(s[nt][2], s[nt][3]);
        }
        rs0 += __shfl_xor_sync(0xffffffffu, rs0, 1);
        rs0 += __shfl_xor_sync(0xffffffffu, rs0, 2);
        rs1 += __shfl_xor_sync(0xffffffffu, rs1, 1);
        rs1 += __shfl_xor_sync(0xffffffffu, rs1, 2);
        l0 = l0 * corr0 + rs0;
        l1 = l1 * corr1 + rs1;
#pragma unroll
        for (int nt = 0; nt < 8; nt++) {
            o[nt][0] *= corr0; o[nt][1] *= corr0;
            o[nt][2] *= corr1; o[nt][3] *= corr1;
        }
        __syncwarp();                    // Ps rows are warp-private

        // O += P V   (V == K tile; k-major access -> scalar LDS)
#pragma unroll
        for (int kb = 0; kb < 8; kb++) {
            unsigned a0 = __float_as_uint(Ps[(mr + g)     * FST + kb * 8 + tig]);
            unsigned a1 = __float_as_uint(Ps[(mr + g + 8) * FST + kb * 8 + tig]);
            unsigned a2 = __float_as_uint(Ps[(mr + g)     * FST + kb * 8 + tig + 4]);
            unsigned a3 = __float_as_uint(Ps[(mr + g + 8) * FST + kb * 8 + tig + 4]);
#pragma unroll
            for (int nt = 0; nt < 8; nt++) {
                unsigned b0 = tfr(Kc[(kb * 8 + tig)     * FST + nt * 8 + g]);
                unsigned b1 = tfr(Kc[(kb * 8 + tig + 4) * FST + nt * 8 + g]);
                mma_tf32(o[nt][0], o[nt][1], o[nt][2], o[nt][3],
                         a0, a1, a2, a3, b0, b1);
            }
        }
    }

    const float inv0 = 1.f / l0, inv1 = 1.f / l1;
    float* Oh = O + (long long)(rowBlk * 128) * DD + h * DHD;
#pragma unroll
    for (int nt = 0; nt < 8; nt++) {
        const int c = nt * 8 + 2 * tig;
        *(float2*)&Oh[(long long)(mr + g)     * DD + c] =
            make_float2(o[nt][0] * inv0, o[nt][1] * inv0);
        *(float2*)&Oh[(long long)(mr + g + 8) * DD + c] =
            make_float2(o[nt][2] * inv1, o[nt][3] * inv1);
    }
}

// ---------------- single-pass add + LayerNorm --------------------------------
__global__ __launch_bounds__(256)
void add_ln_kernel(const float* __restrict__ a, const float* __restrict__ b,
                   const float* __restrict__ gamma, const float* __restrict__ beta,
                   float* __restrict__ out)
{
    const int row = blockIdx.x;
    const int tid = threadIdx.x;
    const float* pa = a + (long long)row * DD;
    const float* pb = b + (long long)row * DD;
    __shared__ float red[256];

    float v[4];
    float s = 0.f;
#pragma unroll
    for (int i = 0; i < 4; i++) {
        const int c = tid + i * 256;
        v[i] = pa[c] + pb[c];
        s += v[i];
    }
    red[tid] = s; __syncthreads();
    for (int o = 128; o; o >>= 1) { if (tid < o) red[tid] += red[tid + o]; __syncthreads(); }
    const float mu = red[0] * (1.f / DD); __syncthreads();

    float var = 0.f;
#pragma unroll
    for (int i = 0; i < 4; i++) { const float d = v[i] - mu; var += d * d; }
    red[tid] = var; __syncthreads();
    for (int o = 128; o; o >>= 1) { if (tid < o) red[tid] += red[tid + o]; __syncthreads(); }
    const float rs = rsqrtf(red[0] * (1.f / DD) + 1e-5f); __syncthreads();

#pragma unroll
    for (int i = 0; i < 4; i++) {
        const int c = tid + i * 256;
        out[(long long)row * DD + c] = (v[i] - mu) * rs * gamma[c] + beta[c];
    }
}

// ---------------- orchestration ----------------------------------------------
extern "C" void kernel_launch(void* const* d_in, const int* in_sizes, int n_in,
                              void* d_out, int out_size)
{
    const float* y    = (const float*)d_in[0];
    const float* enc  = (const float*)d_in[1];
    const float* Wqs  = (const float*)d_in[2];
    const float* bqs  = (const float*)d_in[3];
    const float* Wqc  = (const float*)d_in[4];
    const float* bqc  = (const float*)d_in[5];
    const float* g1   = (const float*)d_in[6];
    const float* be1  = (const float*)d_in[7];
    const float* g2   = (const float*)d_in[8];
    const float* be2  = (const float*)d_in[9];
    const float* g3   = (const float*)d_in[10];
    const float* be3  = (const float*)d_in[11];
    const float* w1   = (const float*)d_in[12];
    const float* b1   = (const float*)d_in[13];
    const float* w2   = (const float*)d_in[14];
    const float* b2   = (const float*)d_in[15];
    float* out = (float*)d_out;

    float *q, *qc, *kc, *tmp, *y1, *y2, *hid;
    cudaGetSymbolAddress((void**)&q,   g_q);
    cudaGetSymbolAddress((void**)&qc,  g_qc);
    cudaGetSymbolAddress((void**)&kc,  g_kc);
    cudaGetSymbolAddress((void**)&tmp, g_tmp);
    cudaGetSymbolAddress((void**)&y1,  g_y1);
    cudaGetSymbolAddress((void**)&y2,  g_y2);
    cudaGetSymbolAddress((void**)&hid, g_hid);

    const long long WST = (long long)DD * DHD;
    const long long QST = (long long)SS * DHD;

    const int GS64  = 3 * (BM * SA + BK * (64 + 8))  * 4;   // 82944
    const int GS128 = 3 * (BM * SA + BK * (128 + 8)) * 4;   // 107520
    const int FSMEM = (2 * 64 * FST + 128 * FST) * 4;       // 69632

    cudaFuncSetAttribute(mma_gemm<64>,
                         cudaFuncAttributeMaxDynamicSharedMemorySize, GS64);
    cudaFuncSetAttribute(mma_gemm<128>,
                         cudaFuncAttributeMaxDynamicSharedMemorySize, GS128);
    cudaFuncSetAttribute(flash_kernel<true>,
                         cudaFuncAttributeMaxDynamicSharedMemorySize, FSMEM);
    cudaFuncSetAttribute(flash_kernel<false>,
                         cudaFuncAttributeMaxDynamicSharedMemorySize, FSMEM);

    // ---- self attention (q = k = v) ----
    mma_gemm<64><<<dim3(1, SS / BM, HH), 256, GS64>>>(
        y, Wqs, bqs, q, DD, DD, DHD, DHD, 0, WST, DHD, QST, 1.f, 0);
    flash_kernel<true><<<dim3(SS / 128, HH), 256, FSMEM>>>(q, q, tmp);
    add_ln_kernel<<<SS, 256>>>(y, tmp, g1, be1, y1);

    // ---- cross attention (k = v) ----
    mma_gemm<64><<<dim3(1, SS / BM, HH), 256, GS64>>>(
        y1, Wqc, bqc, qc, DD, DD, DHD, DHD, 0, WST, DHD, QST, 1.f, 0);
    mma_gemm<64><<<dim3(1, SS / BM, HH), 256, GS64>>>(
        enc, Wqc, bqc, kc, DD, DD, DHD, DHD, 0, WST, DHD, QST, 1.f, 0);
    flash_kernel<false><<<dim3(SS / 128, HH), 256, FSMEM>>>(qc, kc, tmp);
    add_ln_kernel<<<SS, 256>>>(y1, tmp, g2, be2, y2);

    // ---- FFN ----
    mma_gemm<128><<<dim3(HID / 128, SS / BM, 1), 256, GS128>>>(
        y2, w1, b1, hid, DD, DD, HID, HID, 0, 0, 0, 0, 1.f, 1);
    mma_gemm<128><<<dim3(DD / 128, SS / BM, 1), 256, GS128>>>(
        hid, w2, b2, tmp, HID, HID, DD, DD, 0, 0, 0, 0, 1.f, 0);
    add_ln_kernel<<<SS, 256>>>(y2, tmp, g3, be3, out);
}

// round 7
// speedup vs baseline: 1.0610x; 1.0610x over previous
#include <cuda_runtime.h>
#include <math.h>

#define HH  16
#define SS  2048
#define DD  1024
#define DHD 64
#define HID 4096

// ---------------- scratch ----------------------------------------------------
__device__ float g_q   [HH * SS * DHD];
__device__ float g_qc  [HH * SS * DHD];
__device__ float g_kc  [HH * SS * DHD];
__device__ float g_tmp [SS * DD];
__device__ float g_y1  [SS * DD];
__device__ float g_y2  [SS * DD];
__device__ float g_hid [SS * HID];
// rounded-tf32 copies
__device__ float g_yr  [SS * DD];
__device__ float g_y1r [SS * DD];
__device__ float g_y2r [SS * DD];
__device__ float g_wqsr[HH * DD * DHD];
__device__ float g_wqcr[HH * DD * DHD];
__device__ float g_w1r [DD * HID];
__device__ float g_w2r [HID * DD];

// ---------------- helpers ----------------------------------------------------
__device__ __forceinline__ void mma_tf32(
    float& d0, float& d1, float& d2, float& d3,
    unsigned a0, unsigned a1, unsigned a2, unsigned a3,
    unsigned b0, unsigned b1)
{
    asm volatile(
        "mma.sync.aligned.m16n8k8.row.col.f32.tf32.tf32.f32 "
        "{%0,%1,%2,%3}, {%4,%5,%6,%7}, {%8,%9}, {%0,%1,%2,%3};"
        : "+f"(d0), "+f"(d1), "+f"(d2), "+f"(d3)
        : "r"(a0), "r"(a1), "r"(a2), "r"(a3), "r"(b0), "r"(b1));
}
__device__ __forceinline__ void cp16(float* dst, const float* src) {
    unsigned d = (unsigned)__cvta_generic_to_shared(dst);
    asm volatile("cp.async.cg.shared.global [%0], [%1], 16;" :: "r"(d), "l"(src));
}
#define CP_COMMIT() asm volatile("cp.async.commit_group;")
#define CP_WAIT1()  asm volatile("cp.async.wait_group 1;")
#define CP_WAIT0()  asm volatile("cp.async.wait_group 0;")

__device__ __forceinline__ unsigned tfr(float f) {
    unsigned u; asm("cvt.rna.tf32.f32 %0, %1;" : "=r"(u) : "f"(f)); return u;
}
__device__ __forceinline__ void ldsm4(unsigned& r0, unsigned& r1,
                                      unsigned& r2, unsigned& r3, const float* p)
{
    unsigned a = (unsigned)__cvta_generic_to_shared(p);
    asm volatile("ldmatrix.sync.aligned.m8n8.x4.shared.b16 {%0,%1,%2,%3}, [%4];"
                 : "=r"(r0), "=r"(r1), "=r"(r2), "=r"(r3) : "r"(a));
}

// ---------------- one-time rounding pass ------------------------------------
__global__ __launch_bounds__(256)
void round_tf32_kernel(const float* __restrict__ in, float* __restrict__ out, int n4)
{
    for (int i = blockIdx.x * 256 + threadIdx.x; i < n4; i += gridDim.x * 256) {
        float4 v = ((const float4*)in)[i];
        uint4 u;
        u.x = tfr(v.x); u.y = tfr(v.y); u.z = tfr(v.z); u.w = tfr(v.w);
        ((uint4*)out)[i] = u;
    }
}

// ======================= 3-stage cp.async GEMM (raw-bit tf32) ===============
#define BM 128
#define BK 32
#define SA 36

template<int BN>
__global__ __launch_bounds__(256)
void mma_gemm(const float* __restrict__ A, const float* __restrict__ B,
              const float* __restrict__ bias, float* __restrict__ C,
              int K, int lda, int ldb, int ldc,
              long long sA, long long sB, long long sBias, long long sC,
              float alpha, int relu, int round_out)
{
    constexpr int SBNT  = BN + 8;
    constexpr int NT    = BN / 16;
    constexpr int BITER = (BK * BN / 4) / 256;
    constexpr int KSTEP = 256 / (BN / 4);
    constexpr int ABUF  = BM * SA;
    constexpr int BBUF  = BK * SBNT;

    extern __shared__ float sm[];
    float* As = sm;
    float* Bs = sm + 3 * ABUF;

    const int batch = blockIdx.z;
    A += (long long)batch * sA;
    B += (long long)batch * sB;
    C += (long long)batch * sC;
    const float* biasp = bias ? bias + (long long)batch * sBias : nullptr;

    const int rowStart = blockIdx.y * BM;
    const int colStart = blockIdx.x * BN;
    const int nK = K / BK;

    const int tid  = threadIdx.x;
    const int wid  = tid >> 5, lane = tid & 31;
    const int g    = lane >> 2, tig = lane & 3;
    const int warpM = wid & 3, warpN = wid >> 2;

    const int a_m = tid >> 3, a_k = (tid & 7) << 2;
    const float* Agp = A + (long long)(rowStart + a_m) * lda + a_k;

    const int b_r = tid / (BN / 4), b_c = (tid % (BN / 4)) << 2;
    const float* Bgp = B + (long long)b_r * ldb + colStart + b_c;

    const int lm_row = lane & 15;
    const int lm_col = (lane & 16) ? 4 : 0;

    auto issue = [&](int kt) {
        const int k0 = kt * BK;
        float* Ad = As + (kt % 3) * ABUF;
        float* Bd = Bs + (kt % 3) * BBUF;
#pragma unroll
        for (int i = 0; i < 4; i++)
            cp16(Ad + (a_m + 32 * i) * SA + a_k, Agp + (long long)(32 * i) * lda + k0);
#pragma unroll
        for (int i = 0; i < BITER; i++)
            cp16(Bd + (b_r + KSTEP * i) * SBNT + b_c,
                 Bgp + (long long)(KSTEP * i + k0) * ldb);
        CP_COMMIT();
    };

    float acc[2][NT][4];
#pragma unroll
    for (int mt = 0; mt < 2; mt++)
#pragma unroll
        for (int nt = 0; nt < NT; nt++)
#pragma unroll
            for (int i = 0; i < 4; i++) acc[mt][nt][i] = 0.f;

    issue(0);
    if (nK > 1) issue(1);

    for (int kt = 0; kt < nK; kt++) {
        CP_WAIT1();
        __syncthreads();
        if (kt + 2 < nK) issue(kt + 2);

        const float* Ac = As + (kt % 3) * ABUF;
        const float* Bc = Bs + (kt % 3) * BBUF;
#pragma unroll
        for (int ks = 0; ks < 4; ks++) {
            const int kb = ks * 8;
            unsigned af[2][4];
#pragma unroll
            for (int mt = 0; mt < 2; mt++) {
                const int mr = warpM * 32 + mt * 16;
                ldsm4(af[mt][0], af[mt][1], af[mt][2], af[mt][3],
                      &Ac[(mr + lm_row) * SA + kb + lm_col]);
            }
            unsigned bf[NT][2];
#pragma unroll
            for (int nt = 0; nt < NT; nt++) {
                const int nb = warpN * (BN / 2) + nt * 8;
                bf[nt][0] = __float_as_uint(Bc[(kb + tig)     * SBNT + nb + g]);
                bf[nt][1] = __float_as_uint(Bc[(kb + tig + 4) * SBNT + nb + g]);
            }
#pragma unroll
            for (int mt = 0; mt < 2; mt++)
#pragma unroll
                for (int nt = 0; nt < NT; nt++)
                    mma_tf32(acc[mt][nt][0], acc[mt][nt][1], acc[mt][nt][2], acc[mt][nt][3],
                             af[mt][0], af[mt][1], af[mt][2], af[mt][3],
                             bf[nt][0], bf[nt][1]);
        }
    }

#pragma unroll
    for (int mt = 0; mt < 2; mt++) {
        const int r = rowStart + warpM * 32 + mt * 16 + g;
#pragma unroll
        for (int nt = 0; nt < NT; nt++) {
            const int cc = colStart + warpN * (BN / 2) + nt * 8 + 2 * tig;
            const float bb0 = biasp ? biasp[cc]     : 0.f;
            const float bb1 = biasp ? biasp[cc + 1] : 0.f;
            float v0 = acc[mt][nt][0] * alpha + bb0;
            float v1 = acc[mt][nt][1] * alpha + bb1;
            float v2 = acc[mt][nt][2] * alpha + bb0;
            float v3 = acc[mt][nt][3] * alpha + bb1;
            if (relu) { v0 = fmaxf(v0, 0.f); v1 = fmaxf(v1, 0.f);
                        v2 = fmaxf(v2, 0.f); v3 = fmaxf(v3, 0.f); }
            if (round_out) {
                v0 = __uint_as_float(tfr(v0)); v1 = __uint_as_float(tfr(v1));
                v2 = __uint_as_float(tfr(v2)); v3 = __uint_as_float(tfr(v3));
            }
            *(float2*)&C[(long long)r       * ldc + cc] = make_float2(v0, v1);
            *(float2*)&C[(long long)(r + 8) * ldc + cc] = make_float2(v2, v3);
        }
    }
}

// ======================= fused flash attention (pre-rounded inputs) =========
#define FST 68

template<bool CAUSAL>
__global__ __launch_bounds__(256)
void flash_kernel(const float* __restrict__ Q, const float* __restrict__ KV,
                  float* __restrict__ O)
{
    extern __shared__ float sm[];
    float* Ks = sm;                  // 2 * 64 * FST
    float* Ps = sm + 2 * 64 * FST;   // 128 * FST

    const int h = blockIdx.y;
    const int rowBlk = CAUSAL ? (gridDim.x - 1 - blockIdx.x) : blockIdx.x;
    const float* Qh = Q  + (long long)h * SS * DHD + (long long)rowBlk * 128 * DHD;
    const float* Kh = KV + (long long)h * SS * DHD;

    const int tid = threadIdx.x, wid = tid >> 5, lane = tid & 31;
    const int g = lane >> 2, tig = lane & 3;
    const int mr = wid * 16;

    const int k_r = tid >> 2, k_c = (tid & 3) << 4;

    auto issueK = [&](int t) {
        float* Kd = Ks + (t & 1) * 64 * FST;
        const float* src = Kh + (long long)(t * 64 + k_r) * DHD + k_c;
#pragma unroll
        for (int i = 0; i < 4; i++)
            cp16(Kd + k_r * FST + k_c + 4 * i, src + 4 * i);
        CP_COMMIT();
    };

    for (int i = tid; i < 128 * 16; i += 256) {
        int r = i >> 4, c4 = (i & 15) << 2;
        *(float4*)&Ps[r * FST + c4] = *(const float4*)(Qh + r * DHD + c4);
    }
    issueK(0);
    __syncthreads();
    unsigned qf[8][4];
#pragma unroll
    for (int kb = 0; kb < 8; kb++) {
        qf[kb][0] = __float_as_uint(Ps[(mr + g)     * FST + kb * 8 + tig]);
        qf[kb][1] = __float_as_uint(Ps[(mr + g + 8) * FST + kb * 8 + tig]);
        qf[kb][2] = __float_as_uint(Ps[(mr + g)     * FST + kb * 8 + tig + 4]);
        qf[kb][3] = __float_as_uint(Ps[(mr + g + 8) * FST + kb * 8 + tig + 4]);
    }

    float o[8][4];
#pragma unroll
    for (int nt = 0; nt < 8; nt++)
#pragma unroll
        for (int i = 0; i < 4; i++) o[nt][i] = 0.f;
    float m0 = -1e30f, m1 = -1e30f, l0 = 0.f, l1 = 0.f;

    const int nTiles = CAUSAL ? 2 * (rowBlk + 1) : SS / 64;
    const int r0 = rowBlk * 128 + mr + g;
    const int r1 = r0 + 8;

    const int kl_row = (lane & 7) + ((lane & 16) ? 8 : 0);
    const int kl_col = (lane & 8) ? 4 : 0;

    for (int t = 0; t < nTiles; t++) {
        CP_WAIT0();
        __syncthreads();
        if (t + 1 < nTiles) issueK(t + 1);
        const float* Kc = Ks + (t & 1) * 64 * FST;

        // S = Q K^T
        float s[8][4];
#pragma unroll
        for (int nt = 0; nt < 8; nt++) { s[nt][0] = s[nt][1] = s[nt][2] = s[nt][3] = 0.f; }
#pragma unroll
        for (int kb = 0; kb < 8; kb++) {
#pragma unroll
            for (int ntp = 0; ntp < 4; ntp++) {
                unsigned b00, b01, b10, b11;
                ldsm4(b00, b01, b10, b11,
                      &Kc[(ntp * 16 + kl_row) * FST + kb * 8 + kl_col]);
                mma_tf32(s[2*ntp][0], s[2*ntp][1], s[2*ntp][2], s[2*ntp][3],
                         qf[kb][0], qf[kb][1], qf[kb][2], qf[kb][3], b00, b01);
                mma_tf32(s[2*ntp+1][0], s[2*ntp+1][1], s[2*ntp+1][2], s[2*ntp+1][3],
                         qf[kb][0], qf[kb][1], qf[kb][2], qf[kb][3], b10, b11);
            }
        }

        // scale + mask + online softmax
        const int cb = t * 64;
        float tm0 = -1e30f, tm1 = -1e30f;
#pragma unroll
        for (int nt = 0; nt < 8; nt++) {
            const int c0 = cb + nt * 8 + 2 * tig, c1 = c0 + 1;
            s[nt][0] *= 0.125f; s[nt][1] *= 0.125f;
            s[nt][2] *= 0.125f; s[nt][3] *= 0.125f;
            if (CAUSAL) {
                if (c0 > r0) s[nt][0] = -1e30f;
                if (c1 > r0) s[nt][1] = -1e30f;
                if (c0 > r1) s[nt][2] = -1e30f;
                if (c1 > r1) s[nt][3] = -1e30f;
            }
            tm0 = fmaxf(tm0, fmaxf(s[nt][0], s[nt][1]));
            tm1 = fmaxf(tm1, fmaxf(s[nt][2], s[nt][3]));
        }
        tm0 = fmaxf(tm0, __shfl_xor_sync(0xffffffffu, tm0, 1));
        tm0 = fmaxf(tm0, __shfl_xor_sync(0xffffffffu, tm0, 2));
        tm1 = fmaxf(tm1, __shfl_xor_sync(0xffffffffu, tm1, 1));
        tm1 = fmaxf(tm1, __shfl_xor_sync(0xffffffffu, tm1, 2));

        const float mn0 = fmaxf(m0, tm0), mn1 = fmaxf(m1, tm1);
        const float corr0 = __expf(m0 - mn0), corr1 = __expf(m1 - mn1);
        m0 = mn0; m1 = mn1;

        float rs0 = 0.f, rs1 = 0.f;
#pragma unroll
        for (int nt = 0; nt < 8; nt++) {
            s[nt][0] = __expf(s[nt][0] - mn0); rs0 += s[nt][0];
            s[nt][1] = __expf(s[nt][1] - mn0); rs0 += s[nt][1];
            s[nt][2] = __expf(s[nt][2] - mn1); rs1 += s[nt][2];
            s[nt][3] = __expf(s[nt][3] - mn1); rs1 += s[nt][3];
            // store RNA-rounded P bits (one-time cost, off the mma path)
            *(uint2*)&Ps[(mr + g)     * FST + nt * 8 + 2 * tig] =
                make_uint2(tfr(s[nt][0]), tfr(s[nt][1]));
            *(uint2*)&Ps[(mr + g + 8) * FST + nt * 8 + 2 * tig] =
                make_uint2(tfr(s[nt][2]), tfr(s[nt][3]));
        }
        rs0 += __shfl_xor_sync(0xffffffffu, rs0, 1);
        rs0 += __shfl_xor_sync(0xffffffffu, rs0, 2);
        rs1 += __shfl_xor_sync(0xffffffffu, rs1, 1);
        rs1 += __shfl_xor_sync(0xffffffffu, rs1, 2);
        l0 = l0 * corr0 + rs0;
        l1 = l1 * corr1 + rs1;
#pragma unroll
        for (int nt = 0; nt < 8; nt++) {
            o[nt][0] *= corr0; o[nt][1] *= corr0;
            o[nt][2] *= corr1; o[nt][3] *= corr1;
        }
        __syncwarp();

        // O += P V  (V == K tile)
#pragma unroll
        for (int kb = 0; kb < 8; kb++) {
            unsigned a0 = __float_as_uint(Ps[(mr + g)     * FST + kb * 8 + tig]);
            unsigned a1 = __float_as_uint(Ps[(mr + g + 8) * FST + kb * 8 + tig]);
            unsigned a2 = __float_as_uint(Ps[(mr + g)     * FST + kb * 8 + tig + 4]);
            unsigned a3 = __float_as_uint(Ps[(mr + g + 8) * FST + kb * 8 + tig + 4]);
#pragma unroll
            for (int nt = 0; nt < 8; nt++) {
                unsigned b0 = __float_as_uint(Kc[(kb * 8 + tig)     * FST + nt * 8 + g]);
                unsigned b1 = __float_as_uint(Kc[(kb * 8 + tig + 4) * FST + nt * 8 + g]);
                mma_tf32(o[nt][0], o[nt][1], o[nt][2], o[nt][3],
                         a0, a1, a2, a3, b0, b1);
            }
        }
    }

    const float inv0 = 1.f / l0, inv1 = 1.f / l1;
    float* Oh = O + (long long)(rowBlk * 128) * DD + h * DHD;
#pragma unroll
    for (int nt = 0; nt < 8; nt++) {
        const int c = nt * 8 + 2 * tig;
        *(float2*)&Oh[(long long)(mr + g)     * DD + c] =
            make_float2(o[nt][0] * inv0, o[nt][1] * inv0);
        *(float2*)&Oh[(long long)(mr + g + 8) * DD + c] =
            make_float2(o[nt][2] * inv1, o[nt][3] * inv1);
    }
}

// ---------------- add + LayerNorm (exact out + optional rounded copy) --------
__global__ __launch_bounds__(256)
void add_ln_kernel(const float* __restrict__ a, const float* __restrict__ b,
                   const float* __restrict__ gamma, const float* __restrict__ beta,
                   float* __restrict__ out, float* __restrict__ rout)
{
    const int row = blockIdx.x;
    const int tid = threadIdx.x;
    const float* pa = a + (long long)row * DD;
    const float* pb = b + (long long)row * DD;
    __shared__ float red[256];

    float v[4];
    float s = 0.f;
#pragma unroll
    for (int i = 0; i < 4; i++) {
        const int c = tid + i * 256;
        v[i] = pa[c] + pb[c];
        s += v[i];
    }
    red[tid] = s; __syncthreads();
    for (int o = 128; o; o >>= 1) { if (tid < o) red[tid] += red[tid + o]; __syncthreads(); }
    const float mu = red[0] * (1.f / DD); __syncthreads();

    float var = 0.f;
#pragma unroll
    for (int i = 0; i < 4; i++) { const float d = v[i] - mu; var += d * d; }
    red[tid] = var; __syncthreads();
    for (int o = 128; o; o >>= 1) { if (tid < o) red[tid] += red[tid + o]; __syncthreads(); }
    const float rs = rsqrtf(red[0] * (1.f / DD) + 1e-5f); __syncthreads();

#pragma unroll
    for (int i = 0; i < 4; i++) {
        const int c = tid + i * 256;
        const float ov = (v[i] - mu) * rs * gamma[c] + beta[c];
        out[(long long)row * DD + c] = ov;
        if (rout) rout[(long long)row * DD + c] = __uint_as_float(tfr(ov));
    }
}

// ---------------- orchestration ----------------------------------------------
extern "C" void kernel_launch(void* const* d_in, const int* in_sizes, int n_in,
                              void* d_out, int out_size)
{
    const float* y    = (const float*)d_in[0];
    const float* enc  = (const float*)d_in[1];
    const float* Wqs  = (const float*)d_in[2];
    const float* bqs  = (const float*)d_in[3];
    const float* Wqc  = (const float*)d_in[4];
    const float* bqc  = (const float*)d_in[5];
    const float* g1   = (const float*)d_in[6];
    const float* be1  = (const float*)d_in[7];
    const float* g2   = (const float*)d_in[8];
    const float* be2  = (const float*)d_in[9];
    const float* g3   = (const float*)d_in[10];
    const float* be3  = (const float*)d_in[11];
    const float* w1   = (const float*)d_in[12];
    const float* b1   = (const float*)d_in[13];
    const float* w2   = (const float*)d_in[14];
    const float* b2   = (const float*)d_in[15];
    float* out = (float*)d_out;

    float *q, *qc, *kc, *tmp, *y1, *y2, *hid;
    float *yr, *y1r, *y2r, *wqsr, *wqcr, *w1r, *w2r;
    cudaGetSymbolAddress((void**)&q,    g_q);
    cudaGetSymbolAddress((void**)&qc,   g_qc);
    cudaGetSymbolAddress((void**)&kc,   g_kc);
    cudaGetSymbolAddress((void**)&tmp,  g_tmp);
    cudaGetSymbolAddress((void**)&y1,   g_y1);
    cudaGetSymbolAddress((void**)&y2,   g_y2);
    cudaGetSymbolAddress((void**)&hid,  g_hid);
    cudaGetSymbolAddress((void**)&yr,   g_yr);
    cudaGetSymbolAddress((void**)&y1r,  g_y1r);
    cudaGetSymbolAddress((void**)&y2r,  g_y2r);
    cudaGetSymbolAddress((void**)&wqsr, g_wqsr);
    cudaGetSymbolAddress((void**)&wqcr, g_wqcr);
    cudaGetSymbolAddress((void**)&w1r,  g_w1r);
    cudaGetSymbolAddress((void**)&w2r,  g_w2r);

    const long long WST = (long long)DD * DHD;
    const long long QST = (long long)SS * DHD;

    const int GS64  = 3 * (BM * SA + BK * (64 + 8))  * 4;   // 82944
    const int GS128 = 3 * (BM * SA + BK * (128 + 8)) * 4;   // 107520
    const int FSMEM = (2 * 64 * FST + 128 * FST) * 4;       // 69632

    cudaFuncSetAttribute(mma_gemm<64>,
                         cudaFuncAttributeMaxDynamicSharedMemorySize, GS64);
    cudaFuncSetAttribute(mma_gemm<128>,
                         cudaFuncAttributeMaxDynamicSharedMemorySize, GS128);
    cudaFuncSetAttribute(flash_kernel<true>,
                         cudaFuncAttributeMaxDynamicSharedMemorySize, FSMEM);
    cudaFuncSetAttribute(flash_kernel<false>,
                         cudaFuncAttributeMaxDynamicSharedMemorySize, FSMEM);

    // ---- one-time RNA rounding of GEMM inputs ----
    round_tf32_kernel<<<592, 256>>>(Wqs, wqsr, HH * DD * DHD / 4);
    round_tf32_kernel<<<592, 256>>>(Wqc, wqcr, HH * DD * DHD / 4);
    round_tf32_kernel<<<592, 256>>>(w1,  w1r,  DD * HID / 4);
    round_tf32_kernel<<<592, 256>>>(w2,  w2r,  HID * DD / 4);
    round_tf32_kernel<<<592, 256>>>(y,   yr,   SS * DD / 4);

    // ---- self attention (q = k = v) ----
    mma_gemm<64><<<dim3(1, SS / BM, HH), 256, GS64>>>(
        yr, wqsr, bqs, q, DD, DD, DHD, DHD, 0, WST, DHD, QST, 1.f, 0, 1);
    flash_kernel<true><<<dim3(SS / 128, HH), 256, FSMEM>>>(q, q, tmp);
    add_ln_kernel<<<SS, 256>>>(y, tmp, g1, be1, y1, y1r);

    // ---- cross attention (k = v) ----
    mma_gemm<64><<<dim3(1, SS / BM, HH), 256, GS64>>>(
        y1r, wqcr, bqc, qc, DD, DD, DHD, DHD, 0, WST, DHD, QST, 1.f, 0, 1);
    // enc feeds only this GEMM; round via epilogue of the GEMM is not possible
    // for its input, so round enc inline: reuse yr buffer? No -- enc needs its
    // own rounded copy only for the A-side of this projection.
    mma_gemm<64><<<dim3(1, SS / BM, HH), 256, GS64>>>(
        enc, wqcr, bqc, kc, DD, DD, DHD, DHD, 0, WST, DHD, QST, 1.f, 0, 1);
    flash_kernel<false><<<dim3(SS / 128, HH), 256, FSMEM>>>(qc, kc, tmp);
    add_ln_kernel<<<SS, 256>>>(y1, tmp, g2, be2, y2, y2r);

    // ---- FFN ----
    mma_gemm<128><<<dim3(HID / 128, SS / BM, 1), 256, GS128>>>(
        y2r, w1r, b1, hid, DD, DD, HID, HID, 0, 0, 0, 0, 1.f, 1, 1);
    mma_gemm<128><<<dim3(DD / 128, SS / BM, 1), 256, GS128>>>(
        hid, w2r, b2, tmp, HID, HID, DD, DD, 0, 0, 0, 0, 1.f, 0, 0);
    add_ln_kernel<<<SS, 256>>>(y2, tmp, g3, be3, out, nullptr);
}

// round 8
// speedup vs baseline: 1.9107x; 1.8008x over previous
#include <cuda_runtime.h>
#include <cuda_fp16.h>
#include <math.h>

#define HH  16
#define SS  2048
#define DD  1024
#define DHD 64
#define HID 4096

// ---------------- scratch ----------------------------------------------------
__device__ float g_tmp [SS * DD];
__device__ float g_y1  [SS * DD];
__device__ float g_y2  [SS * DD];
__device__ __align__(16) __half g_qh  [HH * SS * DHD];
__device__ __align__(16) __half g_qch [HH * SS * DHD];
__device__ __align__(16) __half g_kch [HH * SS * DHD];
__device__ __align__(16) __half g_yh  [SS * DD];
__device__ __align__(16) __half g_y1h [SS * DD];
__device__ __align__(16) __half g_y2h [SS * DD];
__device__ __align__(16) __half g_ench[SS * DD];
__device__ __align__(16) __half g_wqst[HH * DHD * DD];   // [h][n=64][k=1024]
__device__ __align__(16) __half g_wqct[HH * DHD * DD];
__device__ __align__(16) __half g_w1t [HID * DD];        // [n=4096][k=1024]
__device__ __align__(16) __half g_w2t [DD * HID];        // [n=1024][k=4096]
__device__ __align__(16) __half g_hidh[SS * HID];

// ---------------- helpers ----------------------------------------------------
__device__ __forceinline__ void mma_f16(
    float& d0, float& d1, float& d2, float& d3,
    unsigned a0, unsigned a1, unsigned a2, unsigned a3,
    unsigned b0, unsigned b1)
{
    asm volatile(
        "mma.sync.aligned.m16n8k16.row.col.f32.f16.f16.f32 "
        "{%0,%1,%2,%3}, {%4,%5,%6,%7}, {%8,%9}, {%0,%1,%2,%3};"
        : "+f"(d0), "+f"(d1), "+f"(d2), "+f"(d3)
        : "r"(a0), "r"(a1), "r"(a2), "r"(a3), "r"(b0), "r"(b1));
}
__device__ __forceinline__ void cp16h(__half* dst, const __half* src) {
    unsigned d = (unsigned)__cvta_generic_to_shared(dst);
    asm volatile("cp.async.cg.shared.global [%0], [%1], 16;" :: "r"(d), "l"(src));
}
#define CP_COMMIT() asm volatile("cp.async.commit_group;")
#define CP_WAIT1()  asm volatile("cp.async.wait_group 1;")
#define CP_WAIT0()  asm volatile("cp.async.wait_group 0;")

__device__ __forceinline__ void ldsm4h(unsigned& r0, unsigned& r1,
                                       unsigned& r2, unsigned& r3, const __half* p)
{
    unsigned a = (unsigned)__cvta_generic_to_shared(p);
    asm volatile("ldmatrix.sync.aligned.m8n8.x4.shared.b16 {%0,%1,%2,%3}, [%4];"
                 : "=r"(r0), "=r"(r1), "=r"(r2), "=r"(r3) : "r"(a));
}
__device__ __forceinline__ void ldsm4t(unsigned& r0, unsigned& r1,
                                       unsigned& r2, unsigned& r3, const __half* p)
{
    unsigned a = (unsigned)__cvta_generic_to_shared(p);
    asm volatile("ldmatrix.sync.aligned.m8n8.x4.trans.shared.b16 {%0,%1,%2,%3}, [%4];"
                 : "=r"(r0), "=r"(r1), "=r"(r2), "=r"(r3) : "r"(a));
}

// ---------------- conversion kernels -----------------------------------------
__global__ __launch_bounds__(256)
void f2h_kernel(const float* __restrict__ in, __half* __restrict__ out, int n4)
{
    for (int i = blockIdx.x * 256 + threadIdx.x; i < n4; i += gridDim.x * 256) {
        float4 v = ((const float4*)in)[i];
        ((__half2*)out)[2 * i]     = __floats2half2_rn(v.x, v.y);
        ((__half2*)out)[2 * i + 1] = __floats2half2_rn(v.z, v.w);
    }
}

// transpose + convert: in [R][C] f32 -> out [C][R] half, batched over z
__global__ void conv_trans_kernel(const float* __restrict__ in,
                                  __half* __restrict__ out, int R, int C)
{
    __shared__ float t[32][33];
    const long long bo = (long long)blockIdx.z * R * C;
    in += bo; out += bo;
    const int c0 = blockIdx.x * 32, r0 = blockIdx.y * 32;
    const int tx = threadIdx.x, ty = threadIdx.y;
#pragma unroll
    for (int i = 0; i < 4; i++)
        t[ty + 8 * i][tx] = in[(long long)(r0 + ty + 8 * i) * C + c0 + tx];
    __syncthreads();
#pragma unroll
    for (int i = 0; i < 4; i++)
        out[(long long)(c0 + ty + 8 * i) * R + r0 + tx] = __float2half(t[tx][ty + 8 * i]);
}

// ======================= fp16 tensor-core GEMM ==============================
// A [M][K] half row-major, B [N][K] half row-major (pre-transposed weights).
// C float or Ch half (one non-null). 3-stage cp.async, full-ldmatrix mainloop.
#define BM 128
#define BK 32
#define SAH 40

template<int BN>
__global__ __launch_bounds__(256)
void gemm_h(const __half* __restrict__ A, const __half* __restrict__ B,
            const float* __restrict__ bias, float* __restrict__ C,
            __half* __restrict__ Ch,
            int K, int lda, int ldb, int ldc,
            long long sA, long long sB, long long sBias, long long sC,
            int relu)
{
    constexpr int NTT   = BN / 16;        // n8 tiles per warp (warpN owns BN/2)
    constexpr int ABUF  = BM * SAH;
    constexpr int BBUF  = BN * SAH;
    constexpr int BCH   = BN / 64;        // B chunks per thread

    extern __shared__ __half smh[];
    __half* As = smh;                // 3 * ABUF
    __half* Bs = smh + 3 * ABUF;     // 3 * BBUF

    const int batch = blockIdx.z;
    A += (long long)batch * sA;
    B += (long long)batch * sB;
    if (C)  C  += (long long)batch * sC;
    if (Ch) Ch += (long long)batch * sC;
    const float* biasp = bias ? bias + (long long)batch * sBias : nullptr;

    const int rowStart = blockIdx.y * BM;
    const int colStart = blockIdx.x * BN;
    const int nK = K / BK;

    const int tid  = threadIdx.x;
    const int wid  = tid >> 5, lane = tid & 31;
    const int g    = lane >> 2, tig = lane & 3;
    const int warpM = wid & 3, warpN = wid >> 2;

    // cp.async mappings (16B = 8 halfs)
    const int a_r = tid >> 2, a_c = (tid & 3) << 3;          // 128 rows need 2 passes
    const __half* Agp = A + (long long)(rowStart + a_r) * lda + a_c;
    const int b_r = tid >> 2, b_c = (tid & 3) << 3;
    const __half* Bgp = B + (long long)(colStart + b_r) * ldb + b_c;

    // ldmatrix lane addressing
    const int am_row = lane & 15;
    const int am_col = (lane & 16) ? 8 : 0;
    const int bn_row = (lane & 7) + ((lane & 16) ? 8 : 0);
    const int bn_col = lane & 8;

    auto issue = [&](int kt) {
        const int k0 = kt * BK;
        __half* Ad = As + (kt % 3) * ABUF;
        __half* Bd = Bs + (kt % 3) * BBUF;
        cp16h(Ad + a_r * SAH + a_c,        Agp + k0);
        cp16h(Ad + (a_r + 64) * SAH + a_c, Agp + (long long)64 * lda + k0);
        cp16h(Bd + b_r * SAH + b_c,        Bgp + k0);
        if (BCH == 2)
            cp16h(Bd + (b_r + 64) * SAH + b_c, Bgp + (long long)64 * ldb + k0);
        CP_COMMIT();
    };

    float acc[2][NTT][4];
#pragma unroll
    for (int mt = 0; mt < 2; mt++)
#pragma unroll
        for (int nt = 0; nt < NTT; nt++)
#pragma unroll
            for (int i = 0; i < 4; i++) acc[mt][nt][i] = 0.f;

    issue(0);
    if (nK > 1) issue(1);

    for (int kt = 0; kt < nK; kt++) {
        CP_WAIT1();
        __syncthreads();
        if (kt + 2 < nK) issue(kt + 2);

        const __half* Ac = As + (kt % 3) * ABUF;
        const __half* Bc = Bs + (kt % 3) * BBUF;
#pragma unroll
        for (int ks = 0; ks < 2; ks++) {
            const int ko = ks * 16;
            unsigned af[2][4];
#pragma unroll
            for (int mt = 0; mt < 2; mt++)
                ldsm4h(af[mt][0], af[mt][1], af[mt][2], af[mt][3],
                       Ac + (warpM * 32 + mt * 16 + am_row) * SAH + ko + am_col);
            unsigned bf[NTT][2];
#pragma unroll
            for (int np = 0; np < NTT / 2; np++) {
                const int nb = warpN * (BN / 2) + np * 16;
                unsigned r0, r1, r2, r3;
                ldsm4h(r0, r1, r2, r3, Bc + (nb + bn_row) * SAH + ko + bn_col);
                bf[2 * np][0] = r0;     bf[2 * np][1] = r1;
                bf[2 * np + 1][0] = r2; bf[2 * np + 1][1] = r3;
            }
#pragma unroll
            for (int mt = 0; mt < 2; mt++)
#pragma unroll
                for (int nt = 0; nt < NTT; nt++)
                    mma_f16(acc[mt][nt][0], acc[mt][nt][1], acc[mt][nt][2], acc[mt][nt][3],
                            af[mt][0], af[mt][1], af[mt][2], af[mt][3],
                            bf[nt][0], bf[nt][1]);
        }
    }

#pragma unroll
    for (int mt = 0; mt < 2; mt++) {
        const int r = rowStart + warpM * 32 + mt * 16 + g;
#pragma unroll
        for (int nt = 0; nt < NTT; nt++) {
            const int cc = colStart + warpN * (BN / 2) + nt * 8 + 2 * tig;
            const float bb0 = biasp ? biasp[cc]     : 0.f;
            const float bb1 = biasp ? biasp[cc + 1] : 0.f;
            float v0 = acc[mt][nt][0] + bb0;
            float v1 = acc[mt][nt][1] + bb1;
            float v2 = acc[mt][nt][2] + bb0;
            float v3 = acc[mt][nt][3] + bb1;
            if (relu) { v0 = fmaxf(v0, 0.f); v1 = fmaxf(v1, 0.f);
                        v2 = fmaxf(v2, 0.f); v3 = fmaxf(v3, 0.f); }
            if (Ch) {
                *(__half2*)&Ch[(long long)r       * ldc + cc] = __floats2half2_rn(v0, v1);
                *(__half2*)&Ch[(long long)(r + 8) * ldc + cc] = __floats2half2_rn(v2, v3);
            } else {
                *(float2*)&C[(long long)r       * ldc + cc] = make_float2(v0, v1);
                *(float2*)&C[(long long)(r + 8) * ldc + cc] = make_float2(v2, v3);
            }
        }
    }
}

// ======================= fp16 fused flash attention =========================
// 128 q rows x 1 head per block, 8 warps x 16 rows, 64-row KV tiles (K==V),
// cp.async double-buffered, full-ldmatrix (trans for PV B-frags).
#define KST 72

template<bool CAUSAL>
__global__ __launch_bounds__(256)
void flash_h(const __half* __restrict__ Q, const __half* __restrict__ KV,
             float* __restrict__ O)
{
    extern __shared__ __half smh[];
    __half* Ks = smh;                   // 2 * 64 * KST
    __half* Ps = smh + 2 * 64 * KST;    // 128 * KST

    const int h = blockIdx.y;
    const int rowBlk = CAUSAL ? (gridDim.x - 1 - blockIdx.x) : blockIdx.x;
    const __half* Qh = Q  + (long long)h * SS * DHD + (long long)rowBlk * 128 * DHD;
    const __half* Kh = KV + (long long)h * SS * DHD;

    const int tid = threadIdx.x, wid = tid >> 5, lane = tid & 31;
    const int g = lane >> 2, tig = lane & 3;
    const int mr = wid * 16;

    const int am_row = lane & 15;
    const int am_col = (lane & 16) ? 8 : 0;
    const int bn_row = (lane & 7) + ((lane & 16) ? 8 : 0);
    const int bn_col = lane & 8;
    const int tv_row = (lane & 7) + (lane & 8);
    const int tv_col = (lane & 16) ? 8 : 0;

    const int k_r = tid >> 3, k_c = (tid & 7) << 3;   // 32 rows per pass, 2 passes

    auto issueK = [&](int t) {
        __half* Kd = Ks + (t & 1) * 64 * KST;
        const __half* src = Kh + (long long)(t * 64 + k_r) * DHD + k_c;
        cp16h(Kd + k_r * KST + k_c, src);
        cp16h(Kd + (k_r + 32) * KST + k_c, src + 32 * DHD);
        CP_COMMIT();
    };

    // stage Q through Ps, pull fragments into registers
    for (int i = tid; i < 128 * 8; i += 256) {
        const int r = i >> 3, c8 = (i & 7) << 3;
        *(uint4*)&Ps[r * KST + c8] = *(const uint4*)(Qh + r * DHD + c8);
    }
    issueK(0);
    __syncthreads();
    unsigned qf[4][4];
#pragma unroll
    for (int ks = 0; ks < 4; ks++)
        ldsm4h(qf[ks][0], qf[ks][1], qf[ks][2], qf[ks][3],
               Ps + (mr + am_row) * KST + ks * 16 + am_col);

    float o[8][4];
#pragma unroll
    for (int nt = 0; nt < 8; nt++)
#pragma unroll
        for (int i = 0; i < 4; i++) o[nt][i] = 0.f;
    float m0 = -1e30f, m1 = -1e30f, l0 = 0.f, l1 = 0.f;

    const int nTiles = CAUSAL ? 2 * (rowBlk + 1) : SS / 64;
    const int r0 = rowBlk * 128 + mr + g;
    const int r1 = r0 + 8;

    for (int t = 0; t < nTiles; t++) {
        CP_WAIT0();
        __syncthreads();
        if (t + 1 < nTiles) issueK(t + 1);
        const __half* Kc = Ks + (t & 1) * 64 * KST;

        // S = Q K^T   (A = Q frags, B from Kt[t][e] rows: n=t, k=e)
        float s[8][4];
#pragma unroll
        for (int nt = 0; nt < 8; nt++) { s[nt][0] = s[nt][1] = s[nt][2] = s[nt][3] = 0.f; }
#pragma unroll
        for (int ks = 0; ks < 4; ks++) {
#pragma unroll
            for (int tp = 0; tp < 4; tp++) {
                unsigned b0, b1, b2, b3;
                ldsm4h(b0, b1, b2, b3,
                       Kc + (tp * 16 + bn_row) * KST + ks * 16 + bn_col);
                mma_f16(s[2*tp][0], s[2*tp][1], s[2*tp][2], s[2*tp][3],
                        qf[ks][0], qf[ks][1], qf[ks][2], qf[ks][3], b0, b1);
                mma_f16(s[2*tp+1][0], s[2*tp+1][1], s[2*tp+1][2], s[2*tp+1][3],
                        qf[ks][0], qf[ks][1], qf[ks][2], qf[ks][3], b2, b3);
            }
        }

        // scale + mask + online softmax
        const int cb = t * 64;
        float tm0 = -1e30f, tm1 = -1e30f;
#pragma unroll
        for (int nt = 0; nt < 8; nt++) {
            const int c0 = cb + nt * 8 + 2 * tig, c1 = c0 + 1;
            s[nt][0] *= 0.125f; s[nt][1] *= 0.125f;
            s[nt][2] *= 0.125f; s[nt][3] *= 0.125f;
            if (CAUSAL) {
                if (c0 > r0) s[nt][0] = -1e30f;
                if (c1 > r0) s[nt][1] = -1e30f;
                if (c0 > r1) s[nt][2] = -1e30f;
                if (c1 > r1) s[nt][3] = -1e30f;
            }
            tm0 = fmaxf(tm0, fmaxf(s[nt][0], s[nt][1]));
            tm1 = fmaxf(tm1, fmaxf(s[nt][2], s[nt][3]));
        }
        tm0 = fmaxf(tm0, __shfl_xor_sync(0xffffffffu, tm0, 1));
        tm0 = fmaxf(tm0, __shfl_xor_sync(0xffffffffu, tm0, 2));
        tm1 = fmaxf(tm1, __shfl_xor_sync(0xffffffffu, tm1, 1));
        tm1 = fmaxf(tm1, __shfl_xor_sync(0xffffffffu, tm1, 2));

        const float mn0 = fmaxf(m0, tm0), mn1 = fmaxf(m1, tm1);
        const float corr0 = __expf(m0 - mn0), corr1 = __expf(m1 - mn1);
        m0 = mn0; m1 = mn1;

        float rs0 = 0.f, rs1 = 0.f;
#pragma unroll
        for (int nt = 0; nt < 8; nt++) {
            s[nt][0] = __expf(s[nt][0] - mn0); rs0 += s[nt][0];
            s[nt][1] = __expf(s[nt][1] - mn0); rs0 += s[nt][1];
            s[nt][2] = __expf(s[nt][2] - mn1); rs1 += s[nt][2];
            s[nt][3] = __expf(s[nt][3] - mn1); rs1 += s[nt][3];
            *(__half2*)&Ps[(mr + g)     * KST + nt * 8 + 2 * tig] =
                __floats2half2_rn(s[nt][0], s[nt][1]);
            *(__half2*)&Ps[(mr + g + 8) * KST + nt * 8 + 2 * tig] =
                __floats2half2_rn(s[nt][2], s[nt][3]);
        }
        rs0 += __shfl_xor_sync(0xffffffffu, rs0, 1);
        rs0 += __shfl_xor_sync(0xffffffffu, rs0, 2);
        rs1 += __shfl_xor_sync(0xffffffffu, rs1, 1);
        rs1 += __shfl_xor_sync(0xffffffffu, rs1, 2);
        l0 = l0 * corr0 + rs0;
        l1 = l1 * corr1 + rs1;
#pragma unroll
        for (int nt = 0; nt < 8; nt++) {
            o[nt][0] *= corr0; o[nt][1] *= corr0;
            o[nt][2] *= corr1; o[nt][3] *= corr1;
        }
        __syncwarp();     // Ps rows are warp-private

        // O += P V  (A = P frags from Ps[m][t]; B = Kt[t][e] via ldsm.trans)
#pragma unroll
        for (int ts = 0; ts < 4; ts++) {
            unsigned pf[4];
            ldsm4h(pf[0], pf[1], pf[2], pf[3],
                   Ps + (mr + am_row) * KST + ts * 16 + am_col);
#pragma unroll
            for (int ep = 0; ep < 4; ep++) {
                unsigned b0, b1, b2, b3;
                ldsm4t(b0, b1, b2, b3,
                       Kc + (ts * 16 + tv_row) * KST + ep * 16 + tv_col);
                mma_f16(o[2*ep][0], o[2*ep][1], o[2*ep][2], o[2*ep][3],
                        pf[0], pf[1], pf[2], pf[3], b0, b1);
                mma_f16(o[2*ep+1][0], o[2*ep+1][1], o[2*ep+1][2], o[2*ep+1][3],
                        pf[0], pf[1], pf[2], pf[3], b2, b3);
            }
        }
    }

    const float inv0 = 1.f / l0, inv1 = 1.f / l1;
    float* Oh = O + (long long)(rowBlk * 128) * DD + h * DHD;
#pragma unroll
    for (int nt = 0; nt < 8; nt++) {
        const int c = nt * 8 + 2 * tig;
        *(float2*)&Oh[(long long)(mr + g)     * DD + c] =
            make_float2(o[nt][0] * inv0, o[nt][1] * inv0);
        *(float2*)&Oh[(long long)(mr + g + 8) * DD + c] =
            make_float2(o[nt][2] * inv1, o[nt][3] * inv1);
    }
}

// ---------------- add + LayerNorm (exact f32 out + optional half copy) -------
__global__ __launch_bounds__(256)
void add_ln_kernel(const float* __restrict__ a, const float* __restrict__ b,
                   const float* __restrict__ gamma, const float* __restrict__ beta,
                   float* __restrict__ out, __half* __restrict__ hout)
{
    const int row = blockIdx.x;
    const int tid = threadIdx.x;
    const float* pa = a + (long long)row * DD;
    const float* pb = b + (long long)row * DD;
    __shared__ float red[256];

    float v[4];
    float s = 0.f;
#pragma unroll
    for (int i = 0; i < 4; i++) {
        const int c = tid + i * 256;
        v[i] = pa[c] + pb[c];
        s += v[i];
    }
    red[tid] = s; __syncthreads();
    for (int o = 128; o; o >>= 1) { if (tid < o) red[tid] += red[tid + o]; __syncthreads(); }
    const float mu = red[0] * (1.f / DD); __syncthreads();

    float var = 0.f;
#pragma unroll
    for (int i = 0; i < 4; i++) { const float d = v[i] - mu; var += d * d; }
    red[tid] = var; __syncthreads();
    for (int o = 128; o; o >>= 1) { if (tid < o) red[tid] += red[tid + o]; __syncthreads(); }
    const float rs = rsqrtf(red[0] * (1.f / DD) + 1e-5f); __syncthreads();

#pragma unroll
    for (int i = 0; i < 4; i++) {
        const int c = tid + i * 256;
        const float ov = (v[i] - mu) * rs * gamma[c] + beta[c];
        if (out)  out[(long long)row * DD + c] = ov;
        if (hout) hout[(long long)row * DD + c] = __float2half(ov);
    }
}

// ---------------- orchestration ----------------------------------------------
extern "C" void kernel_launch(void* const* d_in, const int* in_sizes, int n_in,
                              void* d_out, int out_size)
{
    const float* y    = (const float*)d_in[0];
    const float* enc  = (const float*)d_in[1];
    const float* Wqs  = (const float*)d_in[2];
    const float* bqs  = (const float*)d_in[3];
    const float* Wqc  = (const float*)d_in[4];
    const float* bqc  = (const float*)d_in[5];
    const float* g1   = (const float*)d_in[6];
    const float* be1  = (const float*)d_in[7];
    const float* g2   = (const float*)d_in[8];
    const float* be2  = (const float*)d_in[9];
    const float* g3   = (const float*)d_in[10];
    const float* be3  = (const float*)d_in[11];
    const float* w1   = (const float*)d_in[12];
    const float* b1   = (const float*)d_in[13];
    const float* w2   = (const float*)d_in[14];
    const float* b2   = (const float*)d_in[15];
    float* out = (float*)d_out;

    float *tmp, *y1, *y2;
    __half *qh, *qch, *kch, *yh, *y1h, *y2h, *ench, *wqst, *wqct, *w1t, *w2t, *hidh;
    cudaGetSymbolAddress((void**)&tmp,  g_tmp);
    cudaGetSymbolAddress((void**)&y1,   g_y1);
    cudaGetSymbolAddress((void**)&y2,   g_y2);
    cudaGetSymbolAddress((void**)&qh,   g_qh);
    cudaGetSymbolAddress((void**)&qch,  g_qch);
    cudaGetSymbolAddress((void**)&kch,  g_kch);
    cudaGetSymbolAddress((void**)&yh,   g_yh);
    cudaGetSymbolAddress((void**)&y1h,  g_y1h);
    cudaGetSymbolAddress((void**)&y2h,  g_y2h);
    cudaGetSymbolAddress((void**)&ench, g_ench);
    cudaGetSymbolAddress((void**)&wqst, g_wqst);
    cudaGetSymbolAddress((void**)&wqct, g_wqct);
    cudaGetSymbolAddress((void**)&w1t,  g_w1t);
    cudaGetSymbolAddress((void**)&w2t,  g_w2t);
    cudaGetSymbolAddress((void**)&hidh, g_hidh);

    const long long WST = (long long)DHD * DD;   // per-head transposed W stride
    const long long QST = (long long)SS * DHD;

    const int GS64  = 3 * (BM + 64)  * SAH * 2;   // 46080 B
    const int GS128 = 3 * (BM + 128) * SAH * 2;   // 61440 B
    const int FSMEM = (2 * 64 + 128) * KST * 2;   // 36864 B

    cudaFuncSetAttribute(gemm_h<64>,
                         cudaFuncAttributeMaxDynamicSharedMemorySize, GS64);
    cudaFuncSetAttribute(gemm_h<128>,
                         cudaFuncAttributeMaxDynamicSharedMemorySize, GS128);
    cudaFuncSetAttribute(flash_h<true>,
                         cudaFuncAttributeMaxDynamicSharedMemorySize, FSMEM);
    cudaFuncSetAttribute(flash_h<false>,
                         cudaFuncAttributeMaxDynamicSharedMemorySize, FSMEM);

    // ---- conversions (once per launch) ----
    f2h_kernel<<<592, 256>>>(y,   yh,   SS * DD / 4);
    f2h_kernel<<<592, 256>>>(enc, ench, SS * DD / 4);
    conv_trans_kernel<<<dim3(DHD / 32, DD / 32, HH), dim3(32, 8)>>>(Wqs, wqst, DD, DHD);
    conv_trans_kernel<<<dim3(DHD / 32, DD / 32, HH), dim3(32, 8)>>>(Wqc, wqct, DD, DHD);
    conv_trans_kernel<<<dim3(HID / 32, DD / 32, 1),  dim3(32, 8)>>>(w1, w1t, DD, HID);
    conv_trans_kernel<<<dim3(DD / 32, HID / 32, 1),  dim3(32, 8)>>>(w2, w2t, HID, DD);

    // ---- self attention (q = k = v) ----
    gemm_h<64><<<dim3(1, SS / BM, HH), 256, GS64>>>(
        yh, wqst, bqs, nullptr, qh, DD, DD, DD, DHD, 0, WST, DHD, QST, 0);
    flash_h<true><<<dim3(SS / 128, HH), 256, FSMEM>>>(qh, qh, tmp);
    add_ln_kernel<<<SS, 256>>>(y, tmp, g1, be1, y1, y1h);

    // ---- cross attention (k = v) ----
    gemm_h<64><<<dim3(1, SS / BM, HH), 256, GS64>>>(
        y1h, wqct, bqc, nullptr, qch, DD, DD, DD, DHD, 0, WST, DHD, QST, 0);
    gemm_h<64><<<dim3(1, SS / BM, HH), 256, GS64>>>(
        ench, wqct, bqc, nullptr, kch, DD, DD, DD, DHD, 0, WST, DHD, QST, 0);
    flash_h<false><<<dim3(SS / 128, HH), 256, FSMEM>>>(qch, kch, tmp);
    add_ln_kernel<<<SS, 256>>>(y1, tmp, g2, be2, y2, y2h);

    // ---- FFN ----
    gemm_h<128><<<dim3(HID / 128, SS / BM, 1), 256, GS128>>>(
        y2h, w1t, b1, nullptr, hidh, DD, DD, DD, HID, 0, 0, 0, 0, 1);
    gemm_h<128><<<dim3(DD / 128, SS / BM, 1), 256, GS128>>>(
        hidh, w2t, b2, tmp, nullptr, HID, HID, HID, DD, 0, 0, 0, 0, 0);
    add_ln_kernel<<<SS, 256>>>(y2, tmp, g3, be3, out, nullptr);
}

// round 9
// speedup vs baseline: 2.0514x; 1.0736x over previous
#include <cuda_runtime.h>
#include <cuda_fp16.h>
#include <math.h>

#define HH  16
#define SS  2048
#define DD  1024
#define DHD 64
#define HID 4096

// ---------------- scratch ----------------------------------------------------
__device__ float g_tmp [SS * DD];
__device__ float g_y1  [SS * DD];
__device__ float g_y2  [SS * DD];
__device__ __align__(16) __half g_qh  [HH * SS * DHD];
__device__ __align__(16) __half g_qch [HH * SS * DHD];
__device__ __align__(16) __half g_kch [HH * SS * DHD];
__device__ __align__(16) __half g_yh  [SS * DD];
__device__ __align__(16) __half g_y1h [SS * DD];
__device__ __align__(16) __half g_y2h [SS * DD];
__device__ __align__(16) __half g_ench[SS * DD];
__device__ __align__(16) __half g_wqst[HH * DHD * DD];   // [h][n][k]
__device__ __align__(16) __half g_wqct[HH * DHD * DD];
__device__ __align__(16) __half g_w1t [HID * DD];        // [n][k]
__device__ __align__(16) __half g_w2t [DD * HID];
__device__ __align__(16) __half g_hidh[SS * HID];

// ---------------- helpers ----------------------------------------------------
__device__ __forceinline__ void mma_f16(
    float& d0, float& d1, float& d2, float& d3,
    unsigned a0, unsigned a1, unsigned a2, unsigned a3,
    unsigned b0, unsigned b1)
{
    asm volatile(
        "mma.sync.aligned.m16n8k16.row.col.f32.f16.f16.f32 "
        "{%0,%1,%2,%3}, {%4,%5,%6,%7}, {%8,%9}, {%0,%1,%2,%3};"
        : "+f"(d0), "+f"(d1), "+f"(d2), "+f"(d3)
        : "r"(a0), "r"(a1), "r"(a2), "r"(a3), "r"(b0), "r"(b1));
}
__device__ __forceinline__ void cp16h(__half* dst, const __half* src) {
    unsigned d = (unsigned)__cvta_generic_to_shared(dst);
    asm volatile("cp.async.cg.shared.global [%0], [%1], 16;" :: "r"(d), "l"(src));
}
#define CP_COMMIT() asm volatile("cp.async.commit_group;")
#define CP_WAIT1()  asm volatile("cp.async.wait_group 1;")
#define CP_WAIT0()  asm volatile("cp.async.wait_group 0;")

__device__ __forceinline__ void ldsm4h(unsigned& r0, unsigned& r1,
                                       unsigned& r2, unsigned& r3, const __half* p)
{
    unsigned a = (unsigned)__cvta_generic_to_shared(p);
    asm volatile("ldmatrix.sync.aligned.m8n8.x4.shared.b16 {%0,%1,%2,%3}, [%4];"
                 : "=r"(r0), "=r"(r1), "=r"(r2), "=r"(r3) : "r"(a));
}
__device__ __forceinline__ void ldsm4t(unsigned& r0, unsigned& r1,
                                       unsigned& r2, unsigned& r3, const __half* p)
{
    unsigned a = (unsigned)__cvta_generic_to_shared(p);
    asm volatile("ldmatrix.sync.aligned.m8n8.x4.trans.shared.b16 {%0,%1,%2,%3}, [%4];"
                 : "=r"(r0), "=r"(r1), "=r"(r2), "=r"(r3) : "r"(a));
}

// ---------------- conversion kernels -----------------------------------------
__global__ __launch_bounds__(256)
void f2h_kernel(const float* __restrict__ in, __half* __restrict__ out, int n4)
{
    for (int i = blockIdx.x * 256 + threadIdx.x; i < n4; i += gridDim.x * 256) {
        float4 v = ((const float4*)in)[i];
        ((__half2*)out)[2 * i]     = __floats2half2_rn(v.x, v.y);
        ((__half2*)out)[2 * i + 1] = __floats2half2_rn(v.z, v.w);
    }
}

__global__ void conv_trans_kernel(const float* __restrict__ in,
                                  __half* __restrict__ out, int R, int C)
{
    __shared__ float t[32][33];
    const long long bo = (long long)blockIdx.z * R * C;
    in += bo; out += bo;
    const int c0 = blockIdx.x * 32, r0 = blockIdx.y * 32;
    const int tx = threadIdx.x, ty = threadIdx.y;
#pragma unroll
    for (int i = 0; i < 4; i++)
        t[ty + 8 * i][tx] = in[(long long)(r0 + ty + 8 * i) * C + c0 + tx];
    __syncthreads();
#pragma unroll
    for (int i = 0; i < 4; i++)
        out[(long long)(c0 + ty + 8 * i) * R + r0 + tx] = __float2half(t[tx][ty + 8 * i]);
}

// ======================= fp16 tensor-core GEMM (BK=64) ======================
// A [M][K] half row-major, B [N][K] half row-major. 3-stage cp.async.
#define BM 128
#define BK 64
#define SAH 72     // 64 + 8 halfs pad

template<int BN>
__global__ __launch_bounds__(256)
void gemm_h(const __half* __restrict__ A, const __half* __restrict__ B,
            const float* __restrict__ bias, float* __restrict__ C,
            __half* __restrict__ Ch,
            int K, int lda, int ldb, int ldc,
            long long sA, long long sB, long long sBias, long long sC,
            int relu)
{
    constexpr int NTT  = BN / 16;
    constexpr int ABUF = BM * SAH;
    constexpr int BBUF = BN * SAH;
    constexpr int BPASS = BN / 32;            // 32 rows per cp pass

    extern __shared__ __half smh[];
    __half* As = smh;                // 3 * ABUF
    __half* Bs = smh + 3 * ABUF;     // 3 * BBUF

    const int batch = blockIdx.z;
    A += (long long)batch * sA;
    B += (long long)batch * sB;
    if (C)  C  += (long long)batch * sC;
    if (Ch) Ch += (long long)batch * sC;
    const float* biasp = bias ? bias + (long long)batch * sBias : nullptr;

    const int rowStart = blockIdx.y * BM;
    const int colStart = blockIdx.x * BN;
    const int nK = K / BK;

    const int tid  = threadIdx.x;
    const int wid  = tid >> 5, lane = tid & 31;
    const int g    = lane >> 2, tig = lane & 3;
    const int warpM = wid & 3, warpN = wid >> 2;

    const int a_r = tid >> 3, a_c = (tid & 7) << 3;   // 32 rows / pass, 4 passes
    const __half* Agp = A + (long long)(rowStart + a_r) * lda + a_c;
    const __half* Bgp = B + (long long)(colStart + a_r) * ldb + a_c;

    const int am_row = lane & 15;
    const int am_col = (lane & 16) ? 8 : 0;
    const int bn_row = (lane & 7) + ((lane & 16) ? 8 : 0);
    const int bn_col = lane & 8;

    auto issue = [&](int kt) {
        const int k0 = kt * BK;
        __half* Ad = As + (kt % 3) * ABUF;
        __half* Bd = Bs + (kt % 3) * BBUF;
#pragma unroll
        for (int i = 0; i < 4; i++)
            cp16h(Ad + (a_r + 32 * i) * SAH + a_c, Agp + (long long)(32 * i) * lda + k0);
#pragma unroll
        for (int i = 0; i < BPASS; i++)
            cp16h(Bd + (a_r + 32 * i) * SAH + a_c, Bgp + (long long)(32 * i) * ldb + k0);
        CP_COMMIT();
    };

    float acc[2][NTT][4];
#pragma unroll
    for (int mt = 0; mt < 2; mt++)
#pragma unroll
        for (int nt = 0; nt < NTT; nt++)
#pragma unroll
            for (int i = 0; i < 4; i++) acc[mt][nt][i] = 0.f;

    issue(0);
    if (nK > 1) issue(1);

    for (int kt = 0; kt < nK; kt++) {
        CP_WAIT1();
        __syncthreads();
        if (kt + 2 < nK) issue(kt + 2);

        const __half* Ac = As + (kt % 3) * ABUF;
        const __half* Bc = Bs + (kt % 3) * BBUF;
#pragma unroll
        for (int ks = 0; ks < 4; ks++) {
            const int ko = ks * 16;
            unsigned af[2][4];
#pragma unroll
            for (int mt = 0; mt < 2; mt++)
                ldsm4h(af[mt][0], af[mt][1], af[mt][2], af[mt][3],
                       Ac + (warpM * 32 + mt * 16 + am_row) * SAH + ko + am_col);
            unsigned bf[NTT][2];
#pragma unroll
            for (int np = 0; np < NTT / 2; np++) {
                const int nb = warpN * (BN / 2) + np * 16;
                unsigned r0, r1, r2, r3;
                ldsm4h(r0, r1, r2, r3, Bc + (nb + bn_row) * SAH + ko + bn_col);
                bf[2 * np][0] = r0;     bf[2 * np][1] = r1;
                bf[2 * np + 1][0] = r2; bf[2 * np + 1][1] = r3;
            }
#pragma unroll
            for (int mt = 0; mt < 2; mt++)
#pragma unroll
                for (int nt = 0; nt < NTT; nt++)
                    mma_f16(acc[mt][nt][0], acc[mt][nt][1], acc[mt][nt][2], acc[mt][nt][3],
                            af[mt][0], af[mt][1], af[mt][2], af[mt][3],
                            bf[nt][0], bf[nt][1]);
        }
    }

#pragma unroll
    for (int mt = 0; mt < 2; mt++) {
        const int r = rowStart + warpM * 32 + mt * 16 + g;
#pragma unroll
        for (int nt = 0; nt < NTT; nt++) {
            const int cc = colStart + warpN * (BN / 2) + nt * 8 + 2 * tig;
            const float bb0 = biasp ? biasp[cc]     : 0.f;
            const float bb1 = biasp ? biasp[cc + 1] : 0.f;
            float v0 = acc[mt][nt][0] + bb0;
            float v1 = acc[mt][nt][1] + bb1;
            float v2 = acc[mt][nt][2] + bb0;
            float v3 = acc[mt][nt][3] + bb1;
            if (relu) { v0 = fmaxf(v0, 0.f); v1 = fmaxf(v1, 0.f);
                        v2 = fmaxf(v2, 0.f); v3 = fmaxf(v3, 0.f); }
            if (Ch) {
                *(__half2*)&Ch[(long long)r       * ldc + cc] = __floats2half2_rn(v0, v1);
                *(__half2*)&Ch[(long long)(r + 8) * ldc + cc] = __floats2half2_rn(v2, v3);
            } else {
                *(float2*)&C[(long long)r       * ldc + cc] = make_float2(v0, v1);
                *(float2*)&C[(long long)(r + 8) * ldc + cc] = make_float2(v2, v3);
            }
        }
    }
}

// ======================= fp16 fused flash attention =========================
#define KST 72
#define SM_SCALE2 0.18033688f   // 0.125 * log2(e); softmax done in base-2

template<bool CAUSAL>
__global__ __launch_bounds__(256)
void flash_h(const __half* __restrict__ Q, const __half* __restrict__ KV,
             float* __restrict__ O)
{
    extern __shared__ __half smh[];
    __half* Ks = smh;                   // 2 * 64 * KST
    __half* Ps = smh + 2 * 64 * KST;    // 128 * KST

    const int h = blockIdx.y;
    const int rowBlk = CAUSAL ? (gridDim.x - 1 - blockIdx.x) : blockIdx.x;
    const __half* Qh = Q  + (long long)h * SS * DHD + (long long)rowBlk * 128 * DHD;
    const __half* Kh = KV + (long long)h * SS * DHD;

    const int tid = threadIdx.x, wid = tid >> 5, lane = tid & 31;
    const int g = lane >> 2, tig = lane & 3;
    const int mr = wid * 16;

    const int am_row = lane & 15;
    const int am_col = (lane & 16) ? 8 : 0;
    const int bn_row = (lane & 7) + ((lane & 16) ? 8 : 0);
    const int bn_col = lane & 8;
    const int tv_row = (lane & 7) + (lane & 8);
    const int tv_col = (lane & 16) ? 8 : 0;

    const int k_r = tid >> 3, k_c = (tid & 7) << 3;

    auto issueK = [&](int t) {
        __half* Kd = Ks + (t & 1) * 64 * KST;
        const __half* src = Kh + (long long)(t * 64 + k_r) * DHD + k_c;
        cp16h(Kd + k_r * KST + k_c, src);
        cp16h(Kd + (k_r + 32) * KST + k_c, src + 32 * DHD);
        CP_COMMIT();
    };

    for (int i = tid; i < 128 * 8; i += 256) {
        const int r = i >> 3, c8 = (i & 7) << 3;
        *(uint4*)&Ps[r * KST + c8] = *(const uint4*)(Qh + r * DHD + c8);
    }
    issueK(0);
    __syncthreads();
    unsigned qf[4][4];
#pragma unroll
    for (int ks = 0; ks < 4; ks++)
        ldsm4h(qf[ks][0], qf[ks][1], qf[ks][2], qf[ks][3],
               Ps + (mr + am_row) * KST + ks * 16 + am_col);

    float o[8][4];
#pragma unroll
    for (int nt = 0; nt < 8; nt++)
#pragma unroll
        for (int i = 0; i < 4; i++) o[nt][i] = 0.f;
    float m0 = -1e30f, m1 = -1e30f, l0 = 0.f, l1 = 0.f;

    const int nTiles = CAUSAL ? 2 * (rowBlk + 1) : SS / 64;
    const int r0 = rowBlk * 128 + mr + g;
    const int r1 = r0 + 8;

    for (int t = 0; t < nTiles; t++) {
        CP_WAIT0();
        __syncthreads();
        if (t + 1 < nTiles) issueK(t + 1);
        const __half* Kc = Ks + (t & 1) * 64 * KST;

        // S = Q K^T
        float s[8][4];
#pragma unroll
        for (int nt = 0; nt < 8; nt++) { s[nt][0] = s[nt][1] = s[nt][2] = s[nt][3] = 0.f; }
#pragma unroll
        for (int ks = 0; ks < 4; ks++) {
#pragma unroll
            for (int tp = 0; tp < 4; tp++) {
                unsigned b0, b1, b2, b3;
                ldsm4h(b0, b1, b2, b3,
                       Kc + (tp * 16 + bn_row) * KST + ks * 16 + bn_col);
                mma_f16(s[2*tp][0], s[2*tp][1], s[2*tp][2], s[2*tp][3],
                        qf[ks][0], qf[ks][1], qf[ks][2], qf[ks][3], b0, b1);
                mma_f16(s[2*tp+1][0], s[2*tp+1][1], s[2*tp+1][2], s[2*tp+1][3],
                        qf[ks][0], qf[ks][1], qf[ks][2], qf[ks][3], b2, b3);
            }
        }

        // scale (base-2 domain) + mask + online softmax
        const int cb = t * 64;
        float tm0 = -1e30f, tm1 = -1e30f;
#pragma unroll
        for (int nt = 0; nt < 8; nt++) {
            const int c0 = cb + nt * 8 + 2 * tig, c1 = c0 + 1;
            s[nt][0] *= SM_SCALE2; s[nt][1] *= SM_SCALE2;
            s[nt][2] *= SM_SCALE2; s[nt][3] *= SM_SCALE2;
            if (CAUSAL) {
                if (c0 > r0) s[nt][0] = -1e30f;
                if (c1 > r0) s[nt][1] = -1e30f;
                if (c0 > r1) s[nt][2] = -1e30f;
                if (c1 > r1) s[nt][3] = -1e30f;
            }
            tm0 = fmaxf(tm0, fmaxf(s[nt][0], s[nt][1]));
            tm1 = fmaxf(tm1, fmaxf(s[nt][2], s[nt][3]));
        }
        tm0 = fmaxf(tm0, __shfl_xor_sync(0xffffffffu, tm0, 1));
        tm0 = fmaxf(tm0, __shfl_xor_sync(0xffffffffu, tm0, 2));
        tm1 = fmaxf(tm1, __shfl_xor_sync(0xffffffffu, tm1, 1));
        tm1 = fmaxf(tm1, __shfl_xor_sync(0xffffffffu, tm1, 2));

        const float mn0 = fmaxf(m0, tm0), mn1 = fmaxf(m1, tm1);
        const float corr0 = exp2f(m0 - mn0), corr1 = exp2f(m1 - mn1);
        m0 = mn0; m1 = mn1;

        float rs0 = 0.f, rs1 = 0.f;
#pragma unroll
        for (int nt = 0; nt < 8; nt++) {
            s[nt][0] = exp2f(s[nt][0] - mn0); rs0 += s[nt][0];
            s[nt][1] = exp2f(s[nt][1] - mn0); rs0 += s[nt][1];
            s[nt][2] = exp2f(s[nt][2] - mn1); rs1 += s[nt][2];
            s[nt][3] = exp2f(s[nt][3] - mn1); rs1 += s[nt][3];
            *(__half2*)&Ps[(mr + g)     * KST + nt * 8 + 2 * tig] =
                __floats2half2_rn(s[nt][0], s[nt][1]);
            *(__half2*)&Ps[(mr + g + 8) * KST + nt * 8 + 2 * tig] =
                __floats2half2_rn(s[nt][2], s[nt][3]);
        }
        rs0 += __shfl_xor_sync(0xffffffffu, rs0, 1);
        rs0 += __shfl_xor_sync(0xffffffffu, rs0, 2);
        rs1 += __shfl_xor_sync(0xffffffffu, rs1, 1);
        rs1 += __shfl_xor_sync(0xffffffffu, rs1, 2);
        l0 = l0 * corr0 + rs0;
        l1 = l1 * corr1 + rs1;
#pragma unroll
        for (int nt = 0; nt < 8; nt++) {
            o[nt][0] *= corr0; o[nt][1] *= corr0;
            o[nt][2] *= corr1; o[nt][3] *= corr1;
        }
        __syncwarp();

        // O += P V  (V == K tile)
#pragma unroll
        for (int ts = 0; ts < 4; ts++) {
            unsigned pf[4];
            ldsm4h(pf[0], pf[1], pf[2], pf[3],
                   Ps + (mr + am_row) * KST + ts * 16 + am_col);
#pragma unroll
            for (int ep = 0; ep < 4; ep++) {
                unsigned b0, b1, b2, b3;
                ldsm4t(b0, b1, b2, b3,
                       Kc + (ts * 16 + tv_row) * KST + ep * 16 + tv_col);
                mma_f16(o[2*ep][0], o[2*ep][1], o[2*ep][2], o[2*ep][3],
                        pf[0], pf[1], pf[2], pf[3], b0, b1);
                mma_f16(o[2*ep+1][0], o[2*ep+1][1], o[2*ep+1][2], o[2*ep+1][3],
                        pf[0], pf[1], pf[2], pf[3], b2, b3);
            }
        }
    }

    const float inv0 = 1.f / l0, inv1 = 1.f / l1;
    float* Oh = O + (long long)(rowBlk * 128) * DD + h * DHD;
#pragma unroll
    for (int nt = 0; nt < 8; nt++) {
        const int c = nt * 8 + 2 * tig;
        *(float2*)&Oh[(long long)(mr + g)     * DD + c] =
            make_float2(o[nt][0] * inv0, o[nt][1] * inv0);
        *(float2*)&Oh[(long long)(mr + g + 8) * DD + c] =
            make_float2(o[nt][2] * inv1, o[nt][3] * inv1);
    }
}

// ---------------- add + LayerNorm (float4) -----------------------------------
__global__ __launch_bounds__(256)
void add_ln_kernel(const float* __restrict__ a, const float* __restrict__ b,
                   const float* __restrict__ gamma, const float* __restrict__ beta,
                   float* __restrict__ out, __half* __restrict__ hout)
{
    const int row = blockIdx.x;
    const int tid = threadIdx.x;
    const float4* pa = (const float4*)(a + (long long)row * DD);
    const float4* pb = (const float4*)(b + (long long)row * DD);
    __shared__ float red[256];

    float4 v = pa[tid], w = pb[tid];
    v.x += w.x; v.y += w.y; v.z += w.z; v.w += w.w;
    red[tid] = v.x + v.y + v.z + v.w; __syncthreads();
    for (int o = 128; o; o >>= 1) { if (tid < o) red[tid] += red[tid + o]; __syncthreads(); }
    const float mu = red[0] * (1.f / DD); __syncthreads();

    float var = (v.x - mu) * (v.x - mu) + (v.y - mu) * (v.y - mu)
              + (v.z - mu) * (v.z - mu) + (v.w - mu) * (v.w - mu);
    red[tid] = var; __syncthreads();
    for (int o = 128; o; o >>= 1) { if (tid < o) red[tid] += red[tid + o]; __syncthreads(); }
    const float rs = rsqrtf(red[0] * (1.f / DD) + 1e-5f); __syncthreads();

    const float4 gm = ((const float4*)gamma)[tid];
    const float4 bt = ((const float4*)beta)[tid];
    float4 ov;
    ov.x = (v.x - mu) * rs * gm.x + bt.x;
    ov.y = (v.y - mu) * rs * gm.y + bt.y;
    ov.z = (v.z - mu) * rs * gm.z + bt.z;
    ov.w = (v.w - mu) * rs * gm.w + bt.w;
    if (out) ((float4*)(out + (long long)row * DD))[tid] = ov;
    if (hout) {
        __half2* hp = (__half2*)(hout + (long long)row * DD);
        hp[2 * tid]     = __floats2half2_rn(ov.x, ov.y);
        hp[2 * tid + 1] = __floats2half2_rn(ov.z, ov.w);
    }
}

// ---------------- orchestration ----------------------------------------------
extern "C" void kernel_launch(void* const* d_in, const int* in_sizes, int n_in,
                              void* d_out, int out_size)
{
    const float* y    = (const float*)d_in[0];
    const float* enc  = (const float*)d_in[1];
    const float* Wqs  = (const float*)d_in[2];
    const float* bqs  = (const float*)d_in[3];
    const float* Wqc  = (const float*)d_in[4];
    const float* bqc  = (const float*)d_in[5];
    const float* g1   = (const float*)d_in[6];
    const float* be1  = (const float*)d_in[7];
    const float* g2   = (const float*)d_in[8];
    const float* be2  = (const float*)d_in[9];
    const float* g3   = (const float*)d_in[10];
    const float* be3  = (const float*)d_in[11];
    const float* w1   = (const float*)d_in[12];
    const float* b1   = (const float*)d_in[13];
    const float* w2   = (const float*)d_in[14];
    const float* b2   = (const float*)d_in[15];
    float* out = (float*)d_out;

    float *tmp, *y1, *y2;
    __half *qh, *qch, *kch, *yh, *y1h, *y2h, *ench, *wqst, *wqct, *w1t, *w2t, *hidh;
    cudaGetSymbolAddress((void**)&tmp,  g_tmp);
    cudaGetSymbolAddress((void**)&y1,   g_y1);
    cudaGetSymbolAddress((void**)&y2,   g_y2);
    cudaGetSymbolAddress((void**)&qh,   g_qh);
    cudaGetSymbolAddress((void**)&qch,  g_qch);
    cudaGetSymbolAddress((void**)&kch,  g_kch);
    cudaGetSymbolAddress((void**)&yh,   g_yh);
    cudaGetSymbolAddress((void**)&y1h,  g_y1h);
    cudaGetSymbolAddress((void**)&y2h,  g_y2h);
    cudaGetSymbolAddress((void**)&ench, g_ench);
    cudaGetSymbolAddress((void**)&wqst, g_wqst);
    cudaGetSymbolAddress((void**)&wqct, g_wqct);
    cudaGetSymbolAddress((void**)&w1t,  g_w1t);
    cudaGetSymbolAddress((void**)&w2t,  g_w2t);
    cudaGetSymbolAddress((void**)&hidh, g_hidh);

    const long long WST = (long long)DHD * DD;
    const long long QST = (long long)SS * DHD;

    const int GS64  = 3 * (BM + 64)  * SAH * 2;   // 82944 B
    const int GS128 = 3 * (BM + 128) * SAH * 2;   // 110592 B
    const int FSMEM = (2 * 64 + 128) * KST * 2;   // 36864 B

    cudaFuncSetAttribute(gemm_h<64>,
                         cudaFuncAttributeMaxDynamicSharedMemorySize, GS64);
    cudaFuncSetAttribute(gemm_h<128>,
                         cudaFuncAttributeMaxDynamicSharedMemorySize, GS128);
    cudaFuncSetAttribute(flash_h<true>,
                         cudaFuncAttributeMaxDynamicSharedMemorySize, FSMEM);
    cudaFuncSetAttribute(flash_h<false>,
                         cudaFuncAttributeMaxDynamicSharedMemorySize, FSMEM);

    // ---- conversions ----
    f2h_kernel<<<592, 256>>>(y,   yh,   SS * DD / 4);
    f2h_kernel<<<592, 256>>>(enc, ench, SS * DD / 4);
    conv_trans_kernel<<<dim3(DHD / 32, DD / 32, HH), dim3(32, 8)>>>(Wqs, wqst, DD, DHD);
    conv_trans_kernel<<<dim3(DHD / 32, DD / 32, HH), dim3(32, 8)>>>(Wqc, wqct, DD, DHD);
    conv_trans_kernel<<<dim3(HID / 32, DD / 32, 1),  dim3(32, 8)>>>(w1, w1t, DD, HID);
    conv_trans_kernel<<<dim3(DD / 32, HID / 32, 1),  dim3(32, 8)>>>(w2, w2t, HID, DD);

    // ---- self attention (q = k = v) ----
    gemm_h<64><<<dim3(1, SS / BM, HH), 256, GS64>>>(
        yh, wqst, bqs, nullptr, qh, DD, DD, DD, DHD, 0, WST, DHD, QST, 0);
    flash_h<true><<<dim3(SS / 128, HH), 256, FSMEM>>>(qh, qh, tmp);
    add_ln_kernel<<<SS, 256>>>(y, tmp, g1, be1, y1, y1h);

    // ---- cross attention (k = v) ----
    gemm_h<64><<<dim3(1, SS / BM, HH), 256, GS64>>>(
        y1h, wqct, bqc, nullptr, qch, DD, DD, DD, DHD, 0, WST, DHD, QST, 0);
    gemm_h<64><<<dim3(1, SS / BM, HH), 256, GS64>>>(
        ench, wqct, bqc, nullptr, kch, DD, DD, DD, DHD, 0, WST, DHD, QST, 0);
    flash_h<false><<<dim3(SS / 128, HH), 256, FSMEM>>>(qch, kch, tmp);
    add_ln_kernel<<<SS, 256>>>(y1, tmp, g2, be2, y2, y2h);

    // ---- FFN ----
    gemm_h<128><<<dim3(HID / 128, SS / BM, 1), 256, GS128>>>(
        y2h, w1t, b1, nullptr, hidh, DD, DD, DD, HID, 0, 0, 0, 0, 1);
    gemm_h<64><<<dim3(DD / 64, SS / BM, 1), 256, GS64>>>(
        hidh, w2t, b2, tmp, nullptr, HID, HID, HID, DD, 0, 0, 0, 0, 0);
    add_ln_kernel<<<SS, 256>>>(y2, tmp, g3, be3, out, nullptr);
}

// round 10
// speedup vs baseline: 2.1219x; 1.0344x over previous
#include <cuda_runtime.h>
#include <cuda_fp16.h>
#include <math.h>

#define HH  16
#define SS  2048
#define DD  1024
#define DHD 64
#define HID 4096

// ---------------- scratch ----------------------------------------------------
__device__ float g_tmp [SS * DD];
__device__ float g_y1  [SS * DD];
__device__ float g_y2  [SS * DD];
__device__ __align__(16) __half g_qh  [HH * SS * DHD];
__device__ __align__(16) __half g_qch [HH * SS * DHD];
__device__ __align__(16) __half g_kch [HH * SS * DHD];
__device__ __align__(16) __half g_yh  [SS * DD];
__device__ __align__(16) __half g_y1h [SS * DD];
__device__ __align__(16) __half g_y2h [SS * DD];
__device__ __align__(16) __half g_ench[SS * DD];
__device__ __align__(16) __half g_wqst[HH * DHD * DD];   // [h][n][k]
__device__ __align__(16) __half g_wqct[HH * DHD * DD];
__device__ __align__(16) __half g_w1t [HID * DD];        // [n][k]
__device__ __align__(16) __half g_w2t [DD * HID];
__device__ __align__(16) __half g_hidh[SS * HID];

// ---------------- helpers ----------------------------------------------------
__device__ __forceinline__ void mma_f16(
    float& d0, float& d1, float& d2, float& d3,
    unsigned a0, unsigned a1, unsigned a2, unsigned a3,
    unsigned b0, unsigned b1)
{
    asm volatile(
        "mma.sync.aligned.m16n8k16.row.col.f32.f16.f16.f32 "
        "{%0,%1,%2,%3}, {%4,%5,%6,%7}, {%8,%9}, {%0,%1,%2,%3};"
        : "+f"(d0), "+f"(d1), "+f"(d2), "+f"(d3)
        : "r"(a0), "r"(a1), "r"(a2), "r"(a3), "r"(b0), "r"(b1));
}
__device__ __forceinline__ void cp16h(__half* dst, const __half* src) {
    unsigned d = (unsigned)__cvta_generic_to_shared(dst);
    asm volatile("cp.async.cg.shared.global [%0], [%1], 16;" :: "r"(d), "l"(src));
}
#define CP_COMMIT() asm volatile("cp.async.commit_group;")
#define CP_WAIT1()  asm volatile("cp.async.wait_group 1;")
#define CP_WAIT0()  asm volatile("cp.async.wait_group 0;")

__device__ __forceinline__ void ldsm4h(unsigned& r0, unsigned& r1,
                                       unsigned& r2, unsigned& r3, const __half* p)
{
    unsigned a = (unsigned)__cvta_generic_to_shared(p);
    asm volatile("ldmatrix.sync.aligned.m8n8.x4.shared.b16 {%0,%1,%2,%3}, [%4];"
                 : "=r"(r0), "=r"(r1), "=r"(r2), "=r"(r3) : "r"(a));
}
__device__ __forceinline__ void ldsm4t(unsigned& r0, unsigned& r1,
                                       unsigned& r2, unsigned& r3, const __half* p)
{
    unsigned a = (unsigned)__cvta_generic_to_shared(p);
    asm volatile("ldmatrix.sync.aligned.m8n8.x4.trans.shared.b16 {%0,%1,%2,%3}, [%4];"
                 : "=r"(r0), "=r"(r1), "=r"(r2), "=r"(r3) : "r"(a));
}
__device__ __forceinline__ unsigned h2u(float a, float b) {
    __half2 h = __floats2half2_rn(a, b);
    return *(unsigned*)&h;
}

// ---------------- conversion kernels -----------------------------------------
__global__ __launch_bounds__(256)
void f2h2_kernel(const float* __restrict__ in0, __half* __restrict__ out0,
                 const float* __restrict__ in1, __half* __restrict__ out1, int n4)
{
    for (int i = blockIdx.x * 256 + threadIdx.x; i < 2 * n4; i += gridDim.x * 256) {
        const float* in = (i < n4) ? in0 : in1;
        __half* out = (i < n4) ? out0 : out1;
        const int j = (i < n4) ? i : i - n4;
        float4 v = ((const float4*)in)[j];
        ((__half2*)out)[2 * j]     = __floats2half2_rn(v.x, v.y);
        ((__half2*)out)[2 * j + 1] = __floats2half2_rn(v.z, v.w);
    }
}

__global__ void conv_trans_kernel(const float* __restrict__ in,
                                  __half* __restrict__ out, int R, int C)
{
    __shared__ float t[32][33];
    const long long bo = (long long)blockIdx.z * R * C;
    in += bo; out += bo;
    const int c0 = blockIdx.x * 32, r0 = blockIdx.y * 32;
    const int tx = threadIdx.x, ty = threadIdx.y;
#pragma unroll
    for (int i = 0; i < 4; i++)
        t[ty + 8 * i][tx] = in[(long long)(r0 + ty + 8 * i) * C + c0 + tx];
    __syncthreads();
#pragma unroll
    for (int i = 0; i < 4; i++)
        out[(long long)(c0 + ty + 8 * i) * R + r0 + tx] = __float2half(t[tx][ty + 8 * i]);
}

// ======================= fp16 tensor-core GEMM (BK=64) ======================
#define BM 128
#define BK 64
#define SAH 72

template<int BN>
__global__ __launch_bounds__(256)
void gemm_h(const __half* __restrict__ A, const __half* __restrict__ B,
            const float* __restrict__ bias, float* __restrict__ C,
            __half* __restrict__ Ch,
            int K, int lda, int ldb, int ldc,
            long long sA, long long sB, long long sBias, long long sC,
            int relu)
{
    constexpr int NTT  = BN / 16;
    constexpr int ABUF = BM * SAH;
    constexpr int BBUF = BN * SAH;
    constexpr int BPASS = BN / 32;

    extern __shared__ __half smh[];
    __half* As = smh;
    __half* Bs = smh + 3 * ABUF;

    const int batch = blockIdx.z;
    A += (long long)batch * sA;
    B += (long long)batch * sB;
    if (C)  C  += (long long)batch * sC;
    if (Ch) Ch += (long long)batch * sC;
    const float* biasp = bias ? bias + (long long)batch * sBias : nullptr;

    const int rowStart = blockIdx.y * BM;
    const int colStart = blockIdx.x * BN;
    const int nK = K / BK;

    const int tid  = threadIdx.x;
    const int wid  = tid >> 5, lane = tid & 31;
    const int g    = lane >> 2, tig = lane & 3;
    const int warpM = wid & 3, warpN = wid >> 2;

    const int a_r = tid >> 3, a_c = (tid & 7) << 3;
    const __half* Agp = A + (long long)(rowStart + a_r) * lda + a_c;
    const __half* Bgp = B + (long long)(colStart + a_r) * ldb + a_c;

    const int am_row = lane & 15;
    const int am_col = (lane & 16) ? 8 : 0;
    const int bn_row = (lane & 7) + ((lane & 16) ? 8 : 0);
    const int bn_col = lane & 8;

    auto issue = [&](int kt) {
        const int k0 = kt * BK;
        __half* Ad = As + (kt % 3) * ABUF;
        __half* Bd = Bs + (kt % 3) * BBUF;
#pragma unroll
        for (int i = 0; i < 4; i++)
            cp16h(Ad + (a_r + 32 * i) * SAH + a_c, Agp + (long long)(32 * i) * lda + k0);
#pragma unroll
        for (int i = 0; i < BPASS; i++)
            cp16h(Bd + (a_r + 32 * i) * SAH + a_c, Bgp + (long long)(32 * i) * ldb + k0);
        CP_COMMIT();
    };

    float acc[2][NTT][4];
#pragma unroll
    for (int mt = 0; mt < 2; mt++)
#pragma unroll
        for (int nt = 0; nt < NTT; nt++)
#pragma unroll
            for (int i = 0; i < 4; i++) acc[mt][nt][i] = 0.f;

    issue(0);
    if (nK > 1) issue(1);

    for (int kt = 0; kt < nK; kt++) {
        CP_WAIT1();
        __syncthreads();
        if (kt + 2 < nK) issue(kt + 2);

        const __half* Ac = As + (kt % 3) * ABUF;
        const __half* Bc = Bs + (kt % 3) * BBUF;
#pragma unroll
        for (int ks = 0; ks < 4; ks++) {
            const int ko = ks * 16;
            unsigned af[2][4];
#pragma unroll
            for (int mt = 0; mt < 2; mt++)
                ldsm4h(af[mt][0], af[mt][1], af[mt][2], af[mt][3],
                       Ac + (warpM * 32 + mt * 16 + am_row) * SAH + ko + am_col);
            unsigned bf[NTT][2];
#pragma unroll
            for (int np = 0; np < NTT / 2; np++) {
                const int nb = warpN * (BN / 2) + np * 16;
                unsigned r0, r1, r2, r3;
                ldsm4h(r0, r1, r2, r3, Bc + (nb + bn_row) * SAH + ko + bn_col);
                bf[2 * np][0] = r0;     bf[2 * np][1] = r1;
                bf[2 * np + 1][0] = r2; bf[2 * np + 1][1] = r3;
            }
#pragma unroll
            for (int mt = 0; mt < 2; mt++)
#pragma unroll
                for (int nt = 0; nt < NTT; nt++)
                    mma_f16(acc[mt][nt][0], acc[mt][nt][1], acc[mt][nt][2], acc[mt][nt][3],
                            af[mt][0], af[mt][1], af[mt][2], af[mt][3],
                            bf[nt][0], bf[nt][1]);
        }
    }

#pragma unroll
    for (int mt = 0; mt < 2; mt++) {
        const int r = rowStart + warpM * 32 + mt * 16 + g;
#pragma unroll
        for (int nt = 0; nt < NTT; nt++) {
            const int cc = colStart + warpN * (BN / 2) + nt * 8 + 2 * tig;
            const float bb0 = biasp ? biasp[cc]     : 0.f;
            const float bb1 = biasp ? biasp[cc + 1] : 0.f;
            float v0 = acc[mt][nt][0] + bb0;
            float v1 = acc[mt][nt][1] + bb1;
            float v2 = acc[mt][nt][2] + bb0;
            float v3 = acc[mt][nt][3] + bb1;
            if (relu) { v0 = fmaxf(v0, 0.f); v1 = fmaxf(v1, 0.f);
                        v2 = fmaxf(v2, 0.f); v3 = fmaxf(v3, 0.f); }
            if (Ch) {
                *(__half2*)&Ch[(long long)r       * ldc + cc] = __floats2half2_rn(v0, v1);
                *(__half2*)&Ch[(long long)(r + 8) * ldc + cc] = __floats2half2_rn(v2, v3);
            } else {
                *(float2*)&C[(long long)r       * ldc + cc] = make_float2(v0, v1);
                *(float2*)&C[(long long)(r + 8) * ldc + cc] = make_float2(v2, v3);
            }
        }
    }
}

// ======================= fp16 flash attention (P in registers) ==============
#define KST 72
#define SM_SCALE2 0.18033688f   // 0.125 * log2(e)

template<bool CAUSAL>
__global__ __launch_bounds__(256)
void flash_h(const __half* __restrict__ Q, const __half* __restrict__ KV,
             float* __restrict__ O)
{
    extern __shared__ __half smh[];
    __half* Ks = smh;                   // 2 * 64 * KST
    __half* Qs = smh + 2 * 64 * KST;    // 128 * KST (Q staging only)

    const int h = blockIdx.y;
    const int rowBlk = CAUSAL ? (gridDim.x - 1 - blockIdx.x) : blockIdx.x;
    const __half* Qh = Q  + (long long)h * SS * DHD + (long long)rowBlk * 128 * DHD;
    const __half* Kh = KV + (long long)h * SS * DHD;

    const int tid = threadIdx.x, wid = tid >> 5, lane = tid & 31;
    const int g = lane >> 2, tig = lane & 3;
    const int mr = wid * 16;

    const int am_row = lane & 15;
    const int am_col = (lane & 16) ? 8 : 0;
    const int bn_row = (lane & 7) + ((lane & 16) ? 8 : 0);
    const int bn_col = lane & 8;
    const int tv_row = (lane & 7) + (lane & 8);
    const int tv_col = (lane & 16) ? 8 : 0;

    const int k_r = tid >> 3, k_c = (tid & 7) << 3;

    auto issueK = [&](int t) {
        __half* Kd = Ks + (t & 1) * 64 * KST;
        const __half* src = Kh + (long long)(t * 64 + k_r) * DHD + k_c;
        cp16h(Kd + k_r * KST + k_c, src);
        cp16h(Kd + (k_r + 32) * KST + k_c, src + 32 * DHD);
        CP_COMMIT();
    };

    for (int i = tid; i < 128 * 8; i += 256) {
        const int r = i >> 3, c8 = (i & 7) << 3;
        *(uint4*)&Qs[r * KST + c8] = *(const uint4*)(Qh + r * DHD + c8);
    }
    issueK(0);
    __syncthreads();
    unsigned qf[4][4];
#pragma unroll
    for (int ks = 0; ks < 4; ks++)
        ldsm4h(qf[ks][0], qf[ks][1], qf[ks][2], qf[ks][3],
               Qs + (mr + am_row) * KST + ks * 16 + am_col);

    float o[8][4];
#pragma unroll
    for (int nt = 0; nt < 8; nt++)
#pragma unroll
        for (int i = 0; i < 4; i++) o[nt][i] = 0.f;
    float m0 = -1e30f, m1 = -1e30f, l0 = 0.f, l1 = 0.f;

    const int nTiles = CAUSAL ? 2 * (rowBlk + 1) : SS / 64;
    const int r0 = rowBlk * 128 + mr + g;
    const int r1 = r0 + 8;

    for (int t = 0; t < nTiles; t++) {
        CP_WAIT0();
        __syncthreads();
        if (t + 1 < nTiles) issueK(t + 1);
        const __half* Kc = Ks + (t & 1) * 64 * KST;

        // S = Q K^T
        float s[8][4];
#pragma unroll
        for (int nt = 0; nt < 8; nt++) { s[nt][0] = s[nt][1] = s[nt][2] = s[nt][3] = 0.f; }
#pragma unroll
        for (int ks = 0; ks < 4; ks++) {
#pragma unroll
            for (int tp = 0; tp < 4; tp++) {
                unsigned b0, b1, b2, b3;
                ldsm4h(b0, b1, b2, b3,
                       Kc + (tp * 16 + bn_row) * KST + ks * 16 + bn_col);
                mma_f16(s[2*tp][0], s[2*tp][1], s[2*tp][2], s[2*tp][3],
                        qf[ks][0], qf[ks][1], qf[ks][2], qf[ks][3], b0, b1);
                mma_f16(s[2*tp+1][0], s[2*tp+1][1], s[2*tp+1][2], s[2*tp+1][3],
                        qf[ks][0], qf[ks][1], qf[ks][2], qf[ks][3], b2, b3);
            }
        }

        // scale (base-2) + mask + online softmax
        const int cb = t * 64;
        float tm0 = -1e30f, tm1 = -1e30f;
#pragma unroll
        for (int nt = 0; nt < 8; nt++) {
            const int c0 = cb + nt * 8 + 2 * tig, c1 = c0 + 1;
            s[nt][0] *= SM_SCALE2; s[nt][1] *= SM_SCALE2;
            s[nt][2] *= SM_SCALE2; s[nt][3] *= SM_SCALE2;
            if (CAUSAL) {
                if (c0 > r0) s[nt][0] = -1e30f;
                if (c1 > r0) s[nt][1] = -1e30f;
                if (c0 > r1) s[nt][2] = -1e30f;
                if (c1 > r1) s[nt][3] = -1e30f;
            }
            tm0 = fmaxf(tm0, fmaxf(s[nt][0], s[nt][1]));
            tm1 = fmaxf(tm1, fmaxf(s[nt][2], s[nt][3]));
        }
        tm0 = fmaxf(tm0, __shfl_xor_sync(0xffffffffu, tm0, 1));
        tm0 = fmaxf(tm0, __shfl_xor_sync(0xffffffffu, tm0, 2));
        tm1 = fmaxf(tm1, __shfl_xor_sync(0xffffffffu, tm1, 1));
        tm1 = fmaxf(tm1, __shfl_xor_sync(0xffffffffu, tm1, 2));

        const float mn0 = fmaxf(m0, tm0), mn1 = fmaxf(m1, tm1);
        const float corr0 = exp2f(m0 - mn0), corr1 = exp2f(m1 - mn1);
        m0 = mn0; m1 = mn1;

        float rs0 = 0.f, rs1 = 0.f;
        unsigned pf[4][4];                 // A-frags for PV, built in registers
#pragma unroll
        for (int tp = 0; tp < 4; tp++) {
            float* e0 = s[2 * tp];
            float* e1 = s[2 * tp + 1];
            e0[0] = exp2f(e0[0] - mn0); e0[1] = exp2f(e0[1] - mn0);
            e0[2] = exp2f(e0[2] - mn1); e0[3] = exp2f(e0[3] - mn1);
            e1[0] = exp2f(e1[0] - mn0); e1[1] = exp2f(e1[1] - mn0);
            e1[2] = exp2f(e1[2] - mn1); e1[3] = exp2f(e1[3] - mn1);
            rs0 += e0[0] + e0[1] + e1[0] + e1[1];
            rs1 += e0[2] + e0[3] + e1[2] + e1[3];
            // C-frag == A-frag layout (FA2 trick): pack directly
            pf[tp][0] = h2u(e0[0], e0[1]);
            pf[tp][1] = h2u(e0[2], e0[3]);
            pf[tp][2] = h2u(e1[0], e1[1]);
            pf[tp][3] = h2u(e1[2], e1[3]);
        }
        rs0 += __shfl_xor_sync(0xffffffffu, rs0, 1);
        rs0 += __shfl_xor_sync(0xffffffffu, rs0, 2);
        rs1 += __shfl_xor_sync(0xffffffffu, rs1, 1);
        rs1 += __shfl_xor_sync(0xffffffffu, rs1, 2);
        l0 = l0 * corr0 + rs0;
        l1 = l1 * corr1 + rs1;
#pragma unroll
        for (int nt = 0; nt < 8; nt++) {
            o[nt][0] *= corr0; o[nt][1] *= corr0;
            o[nt][2] *= corr1; o[nt][3] *= corr1;
        }

        // O += P V  (P from registers; V == K tile via ldsm.trans)
#pragma unroll
        for (int ts = 0; ts < 4; ts++) {
#pragma unroll
            for (int ep = 0; ep < 4; ep++) {
                unsigned b0, b1, b2, b3;
                ldsm4t(b0, b1, b2, b3,
                       Kc + (ts * 16 + tv_row) * KST + ep * 16 + tv_col);
                mma_f16(o[2*ep][0], o[2*ep][1], o[2*ep][2], o[2*ep][3],
                        pf[ts][0], pf[ts][1], pf[ts][2], pf[ts][3], b0, b1);
                mma_f16(o[2*ep+1][0], o[2*ep+1][1], o[2*ep+1][2], o[2*ep+1][3],
                        pf[ts][0], pf[ts][1], pf[ts][2], pf[ts][3], b2, b3);
            }
        }
    }

    const float inv0 = 1.f / l0, inv1 = 1.f / l1;
    float* Oh = O + (long long)(rowBlk * 128) * DD + h * DHD;
#pragma unroll
    for (int nt = 0; nt < 8; nt++) {
        const int c = nt * 8 + 2 * tig;
        *(float2*)&Oh[(long long)(mr + g)     * DD + c] =
            make_float2(o[nt][0] * inv0, o[nt][1] * inv0);
        *(float2*)&Oh[(long long)(mr + g + 8) * DD + c] =
            make_float2(o[nt][2] * inv1, o[nt][3] * inv1);
    }
}

// ---------------- add + LayerNorm (float4) -----------------------------------
__global__ __launch_bounds__(256)
void add_ln_kernel(const float* __restrict__ a, const float* __restrict__ b,
                   const float* __restrict__ gamma, const float* __restrict__ beta,
                   float* __restrict__ out, __half* __restrict__ hout)
{
    const int row = blockIdx.x;
    const int tid = threadIdx.x;
    const float4* pa = (const float4*)(a + (long long)row * DD);
    const float4* pb = (const float4*)(b + (long long)row * DD);
    __shared__ float red[256];

    float4 v = pa[tid], w = pb[tid];
    v.x += w.x; v.y += w.y; v.z += w.z; v.w += w.w;
    red[tid] = v.x + v.y + v.z + v.w; __syncthreads();
    for (int o = 128; o; o >>= 1) { if (tid < o) red[tid] += red[tid + o]; __syncthreads(); }
    const float mu = red[0] * (1.f / DD); __syncthreads();

    float var = (v.x - mu) * (v.x - mu) + (v.y - mu) * (v.y - mu)
              + (v.z - mu) * (v.z - mu) + (v.w - mu) * (v.w - mu);
    red[tid] = var; __syncthreads();
    for (int o = 128; o; o >>= 1) { if (tid < o) red[tid] += red[tid + o]; __syncthreads(); }
    const float rs = rsqrtf(red[0] * (1.f / DD) + 1e-5f); __syncthreads();

    const float4 gm = ((const float4*)gamma)[tid];
    const float4 bt = ((const float4*)beta)[tid];
    float4 ov;
    ov.x = (v.x - mu) * rs * gm.x + bt.x;
    ov.y = (v.y - mu) * rs * gm.y + bt.y;
    ov.z = (v.z - mu) * rs * gm.z + bt.z;
    ov.w = (v.w - mu) * rs * gm.w + bt.w;
    if (out) ((float4*)(out + (long long)row * DD))[tid] = ov;
    if (hout) {
        __half2* hp = (__half2*)(hout + (long long)row * DD);
        hp[2 * tid]     = __floats2half2_rn(ov.x, ov.y);
        hp[2 * tid + 1] = __floats2half2_rn(ov.z, ov.w);
    }
}

// ---------------- orchestration ----------------------------------------------
extern "C" void kernel_launch(void* const* d_in, const int* in_sizes, int n_in,
                              void* d_out, int out_size)
{
    const float* y    = (const float*)d_in[0];
    const float* enc  = (const float*)d_in[1];
    const float* Wqs  = (const float*)d_in[2];
    const float* bqs  = (const float*)d_in[3];
    const float* Wqc  = (const float*)d_in[4];
    const float* bqc  = (const float*)d_in[5];
    const float* g1   = (const float*)d_in[6];
    const float* be1  = (const float*)d_in[7];
    const float* g2   = (const float*)d_in[8];
    const float* be2  = (const float*)d_in[9];
    const float* g3   = (const float*)d_in[10];
    const float* be3  = (const float*)d_in[11];
    const float* w1   = (const float*)d_in[12];
    const float* b1   = (const float*)d_in[13];
    const float* w2   = (const float*)d_in[14];
    const float* b2   = (const float*)d_in[15];
    float* out = (float*)d_out;

    float *tmp, *y1, *y2;
    __half *qh, *qch, *kch, *yh, *y1h, *y2h, *ench, *wqst, *wqct, *w1t, *w2t, *hidh;
    cudaGetSymbolAddress((void**)&tmp,  g_tmp);
    cudaGetSymbolAddress((void**)&y1,   g_y1);
    cudaGetSymbolAddress((void**)&y2,   g_y2);
    cudaGetSymbolAddress((void**)&qh,   g_qh);
    cudaGetSymbolAddress((void**)&qch,  g_qch);
    cudaGetSymbolAddress((void**)&kch,  g_kch);
    cudaGetSymbolAddress((void**)&yh,   g_yh);
    cudaGetSymbolAddress((void**)&y1h,  g_y1h);
    cudaGetSymbolAddress((void**)&y2h,  g_y2h);
    cudaGetSymbolAddress((void**)&ench, g_ench);
    cudaGetSymbolAddress((void**)&wqst, g_wqst);
    cudaGetSymbolAddress((void**)&wqct, g_wqct);
    cudaGetSymbolAddress((void**)&w1t,  g_w1t);
    cudaGetSymbolAddress((void**)&w2t,  g_w2t);
    cudaGetSymbolAddress((void**)&hidh, g_hidh);

    const long long WST = (long long)DHD * DD;
    const long long QST = (long long)SS * DHD;

    const int GS64  = 3 * (BM + 64)  * SAH * 2;   // 82944 B
    const int GS128 = 3 * (BM + 128) * SAH * 2;   // 110592 B
    const int FSMEM = (2 * 64 + 128) * KST * 2;   // 36864 B

    cudaFuncSetAttribute(gemm_h<64>,
                         cudaFuncAttributeMaxDynamicSharedMemorySize, GS64);
    cudaFuncSetAttribute(gemm_h<128>,
                         cudaFuncAttributeMaxDynamicSharedMemorySize, GS128);
    cudaFuncSetAttribute(flash_h<true>,
                         cudaFuncAttributeMaxDynamicSharedMemorySize, FSMEM);
    cudaFuncSetAttribute(flash_h<false>,
                         cudaFuncAttributeMaxDynamicSharedMemorySize, FSMEM);

    // ---- conversions ----
    f2h2_kernel<<<592, 256>>>(y, yh, enc, ench, SS * DD / 4);
    conv_trans_kernel<<<dim3(DHD / 32, DD / 32, HH), dim3(32, 8)>>>(Wqs, wqst, DD, DHD);
    conv_trans_kernel<<<dim3(DHD / 32, DD / 32, HH), dim3(32, 8)>>>(Wqc, wqct, DD, DHD);
    conv_trans_kernel<<<dim3(HID / 32, DD / 32, 1),  dim3(32, 8)>>>(w1, w1t, DD, HID);
    conv_trans_kernel<<<dim3(DD / 32, HID / 32, 1),  dim3(32, 8)>>>(w2, w2t, HID, DD);

    // ---- self attention (q = k = v) ----
    gemm_h<64><<<dim3(1, SS / BM, HH), 256, GS64>>>(
        yh, wqst, bqs, nullptr, qh, DD, DD, DD, DHD, 0, WST, DHD, QST, 0);
    flash_h<true><<<dim3(SS / 128, HH), 256, FSMEM>>>(qh, qh, tmp);
    add_ln_kernel<<<SS, 256>>>(y, tmp, g1, be1, y1, y1h);

    // ---- cross attention (k = v) ----
    gemm_h<64><<<dim3(1, SS / BM, HH), 256, GS64>>>(
        y1h, wqct, bqc, nullptr, qch, DD, DD, DD, DHD, 0, WST, DHD, QST, 0);
    gemm_h<64><<<dim3(1, SS / BM, HH), 256, GS64>>>(
        ench, wqct, bqc, nullptr, kch, DD, DD, DD, DHD, 0, WST, DHD, QST, 0);
    flash_h<false><<<dim3(SS / 128, HH), 256, FSMEM>>>(qch, kch, tmp);
    add_ln_kernel<<<SS, 256>>>(y1, tmp, g2, be2, y2, y2h);

    // ---- FFN ----
    gemm_h<128><<<dim3(HID / 128, SS / BM, 1), 256, GS128>>>(
        y2h, w1t, b1, nullptr, hidh, DD, DD, DD, HID, 0, 0, 0, 0, 1);
    gemm_h<64><<<dim3(DD / 64, SS / BM, 1), 256, GS64>>>(
        hidh, w2t, b2, tmp, nullptr, HID, HID, HID, DD, 0, 0, 0, 0, 0);
    add_ln_kernel<<<SS, 256>>>(y2, tmp, g3, be3, out, nullptr);
}

// round 11
// speedup vs baseline: 2.2016x; 1.0375x over previous
#include <cuda_runtime.h>
#include <cuda_fp16.h>
#include <math.h>

#define HH  16
#define SS  2048
#define DD  1024
#define DHD 64
#define HID 4096

// ---------------- scratch ----------------------------------------------------
__device__ float g_tmp [SS * DD];
__device__ float g_y1  [SS * DD];
__device__ float g_y2  [SS * DD];
__device__ __align__(16) __half g_qh  [HH * SS * DHD];
__device__ __align__(16) __half g_qch [HH * SS * DHD];
__device__ __align__(16) __half g_kch [HH * SS * DHD];
__device__ __align__(16) __half g_yh  [SS * DD];
__device__ __align__(16) __half g_y1h [SS * DD];
__device__ __align__(16) __half g_y2h [SS * DD];
__device__ __align__(16) __half g_ench[SS * DD];
__device__ __align__(16) __half g_wqst[HH * DHD * DD];
__device__ __align__(16) __half g_wqct[HH * DHD * DD];
__device__ __align__(16) __half g_w1t [HID * DD];
__device__ __align__(16) __half g_w2t [DD * HID];
__device__ __align__(16) __half g_hidh[SS * HID];

// ---------------- helpers ----------------------------------------------------
__device__ __forceinline__ void mma_f16(
    float& d0, float& d1, float& d2, float& d3,
    unsigned a0, unsigned a1, unsigned a2, unsigned a3,
    unsigned b0, unsigned b1)
{
    asm volatile(
        "mma.sync.aligned.m16n8k16.row.col.f32.f16.f16.f32 "
        "{%0,%1,%2,%3}, {%4,%5,%6,%7}, {%8,%9}, {%0,%1,%2,%3};"
        : "+f"(d0), "+f"(d1), "+f"(d2), "+f"(d3)
        : "r"(a0), "r"(a1), "r"(a2), "r"(a3), "r"(b0), "r"(b1));
}
__device__ __forceinline__ void cp16h(__half* dst, const __half* src) {
    unsigned d = (unsigned)__cvta_generic_to_shared(dst);
    asm volatile("cp.async.cg.shared.global [%0], [%1], 16;" :: "r"(d), "l"(src));
}
#define CP_COMMIT() asm volatile("cp.async.commit_group;")
#define CP_WAIT1()  asm volatile("cp.async.wait_group 1;")
#define CP_WAIT0()  asm volatile("cp.async.wait_group 0;")

__device__ __forceinline__ void ldsm4h(unsigned& r0, unsigned& r1,
                                       unsigned& r2, unsigned& r3, const __half* p)
{
    unsigned a = (unsigned)__cvta_generic_to_shared(p);
    asm volatile("ldmatrix.sync.aligned.m8n8.x4.shared.b16 {%0,%1,%2,%3}, [%4];"
                 : "=r"(r0), "=r"(r1), "=r"(r2), "=r"(r3) : "r"(a));
}
__device__ __forceinline__ void ldsm4t(unsigned& r0, unsigned& r1,
                                       unsigned& r2, unsigned& r3, const __half* p)
{
    unsigned a = (unsigned)__cvta_generic_to_shared(p);
    asm volatile("ldmatrix.sync.aligned.m8n8.x4.trans.shared.b16 {%0,%1,%2,%3}, [%4];"
                 : "=r"(r0), "=r"(r1), "=r"(r2), "=r"(r3) : "r"(a));
}
__device__ __forceinline__ unsigned h2u(float a, float b) {
    __half2 h = __floats2half2_rn(a, b);
    return *(unsigned*)&h;
}
// guaranteed single-MUFU exp2
__device__ __forceinline__ float ex2(float x) {
    float y; asm("ex2.approx.ftz.f32 %0, %1;" : "=f"(y) : "f"(x)); return y;
}

// ---------------- conversion kernels -----------------------------------------
__global__ __launch_bounds__(256)
void f2h2_kernel(const float* __restrict__ in0, __half* __restrict__ out0,
                 const float* __restrict__ in1, __half* __restrict__ out1, int n4)
{
    for (int i = blockIdx.x * 256 + threadIdx.x; i < 2 * n4; i += gridDim.x * 256) {
        const float* in = (i < n4) ? in0 : in1;
        __half* out = (i < n4) ? out0 : out1;
        const int j = (i < n4) ? i : i - n4;
        float4 v = ((const float4*)in)[j];
        ((__half2*)out)[2 * j]     = __floats2half2_rn(v.x, v.y);
        ((__half2*)out)[2 * j + 1] = __floats2half2_rn(v.z, v.w);
    }
}

// transpose + convert, optionally two tensors (z split)
__global__ void conv_trans_kernel(const float* __restrict__ in0, __half* __restrict__ out0,
                                  const float* __restrict__ in1, __half* __restrict__ out1,
                                  int R, int C, int zsplit)
{
    __shared__ float t[32][33];
    int z = blockIdx.z;
    const float* in = in0; __half* out = out0;
    if (in1 && z >= zsplit) { in = in1; out = out1; z -= zsplit; }
    const long long bo = (long long)z * R * C;
    in += bo; out += bo;
    const int c0 = blockIdx.x * 32, r0 = blockIdx.y * 32;
    const int tx = threadIdx.x, ty = threadIdx.y;
#pragma unroll
    for (int i = 0; i < 4; i++)
        t[ty + 8 * i][tx] = in[(long long)(r0 + ty + 8 * i) * C + c0 + tx];
    __syncthreads();
#pragma unroll
    for (int i = 0; i < 4; i++)
        out[(long long)(c0 + ty + 8 * i) * R + r0 + tx] = __float2half(t[tx][ty + 8 * i]);
}

// ======================= fp16 tensor-core GEMM (BK=64) ======================
// Optional second input/output pair (A2/Ch2): batches >= HH use them.
#define BM 128
#define BK 64
#define SAH 72

template<int BN>
__global__ __launch_bounds__(256)
void gemm_h(const __half* __restrict__ A, const __half* __restrict__ B,
            const float* __restrict__ bias, float* __restrict__ C,
            __half* __restrict__ Ch,
            const __half* __restrict__ A2, __half* __restrict__ Ch2,
            int K, int lda, int ldb, int ldc,
            long long sA, long long sB, long long sBias, long long sC,
            int relu)
{
    constexpr int NTT  = BN / 16;
    constexpr int ABUF = BM * SAH;
    constexpr int BBUF = BN * SAH;
    constexpr int BPASS = BN / 32;

    extern __shared__ __half smh[];
    __half* As = smh;
    __half* Bs = smh + 3 * ABUF;

    int batch = blockIdx.z;
    if (A2 && batch >= HH) { A = A2; Ch = Ch2; batch -= HH; }
    A += (long long)batch * sA;
    B += (long long)batch * sB;
    if (C)  C  += (long long)batch * sC;
    if (Ch) Ch += (long long)batch * sC;
    const float* biasp = bias ? bias + (long long)batch * sBias : nullptr;

    const int rowStart = blockIdx.y * BM;
    const int colStart = blockIdx.x * BN;
    const int nK = K / BK;

    const int tid  = threadIdx.x;
    const int wid  = tid >> 5, lane = tid & 31;
    const int g    = lane >> 2, tig = lane & 3;
    const int warpM = wid & 3, warpN = wid >> 2;

    const int a_r = tid >> 3, a_c = (tid & 7) << 3;
    const __half* Agp = A + (long long)(rowStart + a_r) * lda + a_c;
    const __half* Bgp = B + (long long)(colStart + a_r) * ldb + a_c;

    const int am_row = lane & 15;
    const int am_col = (lane & 16) ? 8 : 0;
    const int bn_row = (lane & 7) + ((lane & 16) ? 8 : 0);
    const int bn_col = lane & 8;

    auto issue = [&](int kt) {
        const int k0 = kt * BK;
        __half* Ad = As + (kt % 3) * ABUF;
        __half* Bd = Bs + (kt % 3) * BBUF;
#pragma unroll
        for (int i = 0; i < 4; i++)
            cp16h(Ad + (a_r + 32 * i) * SAH + a_c, Agp + (long long)(32 * i) * lda + k0);
#pragma unroll
        for (int i = 0; i < BPASS; i++)
            cp16h(Bd + (a_r + 32 * i) * SAH + a_c, Bgp + (long long)(32 * i) * ldb + k0);
        CP_COMMIT();
    };

    float acc[2][NTT][4];
#pragma unroll
    for (int mt = 0; mt < 2; mt++)
#pragma unroll
        for (int nt = 0; nt < NTT; nt++)
#pragma unroll
            for (int i = 0; i < 4; i++) acc[mt][nt][i] = 0.f;

    issue(0);
    if (nK > 1) issue(1);

    for (int kt = 0; kt < nK; kt++) {
        CP_WAIT1();
        __syncthreads();
        if (kt + 2 < nK) issue(kt + 2);

        const __half* Ac = As + (kt % 3) * ABUF;
        const __half* Bc = Bs + (kt % 3) * BBUF;
#pragma unroll
        for (int ks = 0; ks < 4; ks++) {
            const int ko = ks * 16;
            unsigned af[2][4];
#pragma unroll
            for (int mt = 0; mt < 2; mt++)
                ldsm4h(af[mt][0], af[mt][1], af[mt][2], af[mt][3],
                       Ac + (warpM * 32 + mt * 16 + am_row) * SAH + ko + am_col);
            unsigned bf[NTT][2];
#pragma unroll
            for (int np = 0; np < NTT / 2; np++) {
                const int nb = warpN * (BN / 2) + np * 16;
                unsigned r0, r1, r2, r3;
                ldsm4h(r0, r1, r2, r3, Bc + (nb + bn_row) * SAH + ko + bn_col);
                bf[2 * np][0] = r0;     bf[2 * np][1] = r1;
                bf[2 * np + 1][0] = r2; bf[2 * np + 1][1] = r3;
            }
#pragma unroll
            for (int mt = 0; mt < 2; mt++)
#pragma unroll
                for (int nt = 0; nt < NTT; nt++)
                    mma_f16(acc[mt][nt][0], acc[mt][nt][1], acc[mt][nt][2], acc[mt][nt][3],
                            af[mt][0], af[mt][1], af[mt][2], af[mt][3],
                            bf[nt][0], bf[nt][1]);
        }
    }

#pragma unroll
    for (int mt = 0; mt < 2; mt++) {
        const int r = rowStart + warpM * 32 + mt * 16 + g;
#pragma unroll
        for (int nt = 0; nt < NTT; nt++) {
            const int cc = colStart + warpN * (BN / 2) + nt * 8 + 2 * tig;
            const float bb0 = biasp ? biasp[cc]     : 0.f;
            const float bb1 = biasp ? biasp[cc + 1] : 0.f;
            float v0 = acc[mt][nt][0] + bb0;
            float v1 = acc[mt][nt][1] + bb1;
            float v2 = acc[mt][nt][2] + bb0;
            float v3 = acc[mt][nt][3] + bb1;
            if (relu) { v0 = fmaxf(v0, 0.f); v1 = fmaxf(v1, 0.f);
                        v2 = fmaxf(v2, 0.f); v3 = fmaxf(v3, 0.f); }
            if (Ch) {
                *(__half2*)&Ch[(long long)r       * ldc + cc] = __floats2half2_rn(v0, v1);
                *(__half2*)&Ch[(long long)(r + 8) * ldc + cc] = __floats2half2_rn(v2, v3);
            } else {
                *(float2*)&C[(long long)r       * ldc + cc] = make_float2(v0, v1);
                *(float2*)&C[(long long)(r + 8) * ldc + cc] = make_float2(v2, v3);
            }
        }
    }
}

// ======================= fp16 flash attention ===============================
// P in registers; causal mask applied only to the 2 diagonal tiles.
#define KST 72
#define SM_SCALE2 0.18033688f   // 0.125 * log2(e)

template<bool CAUSAL>
__global__ __launch_bounds__(256)
void flash_h(const __half* __restrict__ Q, const __half* __restrict__ KV,
             float* __restrict__ O)
{
    extern __shared__ __half smh[];
    __half* Ks = smh;                   // 2 * 64 * KST
    __half* Qs = smh + 2 * 64 * KST;    // 128 * KST

    const int h = blockIdx.y;
    const int rowBlk = CAUSAL ? (gridDim.x - 1 - blockIdx.x) : blockIdx.x;
    const __half* Qh = Q  + (long long)h * SS * DHD + (long long)rowBlk * 128 * DHD;
    const __half* Kh = KV + (long long)h * SS * DHD;

    const int tid = threadIdx.x, wid = tid >> 5, lane = tid & 31;
    const int g = lane >> 2, tig = lane & 3;
    const int mr = wid * 16;

    const int am_row = lane & 15;
    const int am_col = (lane & 16) ? 8 : 0;
    const int bn_row = (lane & 7) + ((lane & 16) ? 8 : 0);
    const int bn_col = lane & 8;
    const int tv_row = (lane & 7) + (lane & 8);
    const int tv_col = (lane & 16) ? 8 : 0;

    const int k_r = tid >> 3, k_c = (tid & 7) << 3;

    auto issueK = [&](int t) {
        __half* Kd = Ks + (t & 1) * 64 * KST;
        const __half* src = Kh + (long long)(t * 64 + k_r) * DHD + k_c;
        cp16h(Kd + k_r * KST + k_c, src);
        cp16h(Kd + (k_r + 32) * KST + k_c, src + 32 * DHD);
        CP_COMMIT();
    };

    for (int i = tid; i < 128 * 8; i += 256) {
        const int r = i >> 3, c8 = (i & 7) << 3;
        *(uint4*)&Qs[r * KST + c8] = *(const uint4*)(Qh + r * DHD + c8);
    }
    issueK(0);
    __syncthreads();
    unsigned qf[4][4];
#pragma unroll
    for (int ks = 0; ks < 4; ks++)
        ldsm4h(qf[ks][0], qf[ks][1], qf[ks][2], qf[ks][3],
               Qs + (mr + am_row) * KST + ks * 16 + am_col);

    float o[8][4];
#pragma unroll
    for (int nt = 0; nt < 8; nt++)
#pragma unroll
        for (int i = 0; i < 4; i++) o[nt][i] = 0.f;
    float m0 = -1e30f, m1 = -1e30f, l0 = 0.f, l1 = 0.f;

    const int nTiles = CAUSAL ? 2 * (rowBlk + 1) : SS / 64;
    const int r0 = rowBlk * 128 + mr + g;
    const int r1 = r0 + 8;

    auto tile_body = [&](int t, bool MASKED) {
        CP_WAIT0();
        __syncthreads();
        if (t + 1 < nTiles) issueK(t + 1);
        const __half* Kc = Ks + (t & 1) * 64 * KST;

        // S = Q K^T
        float s[8][4];
#pragma unroll
        for (int nt = 0; nt < 8; nt++) { s[nt][0] = s[nt][1] = s[nt][2] = s[nt][3] = 0.f; }
#pragma unroll
        for (int ks = 0; ks < 4; ks++) {
#pragma unroll
            for (int tp = 0; tp < 4; tp++) {
                unsigned b0, b1, b2, b3;
                ldsm4h(b0, b1, b2, b3,
                       Kc + (tp * 16 + bn_row) * KST + ks * 16 + bn_col);
                mma_f16(s[2*tp][0], s[2*tp][1], s[2*tp][2], s[2*tp][3],
                        qf[ks][0], qf[ks][1], qf[ks][2], qf[ks][3], b0, b1);
                mma_f16(s[2*tp+1][0], s[2*tp+1][1], s[2*tp+1][2], s[2*tp+1][3],
                        qf[ks][0], qf[ks][1], qf[ks][2], qf[ks][3], b2, b3);
            }
        }

        // scale (base-2) + optional mask + online softmax
        const int cb = t * 64;
        float tm0 = -1e30f, tm1 = -1e30f;
#pragma unroll
        for (int nt = 0; nt < 8; nt++) {
            s[nt][0] *= SM_SCALE2; s[nt][1] *= SM_SCALE2;
            s[nt][2] *= SM_SCALE2; s[nt][3] *= SM_SCALE2;
            if (MASKED) {
                const int c0 = cb + nt * 8 + 2 * tig, c1 = c0 + 1;
                if (c0 > r0) s[nt][0] = -1e30f;
                if (c1 > r0) s[nt][1] = -1e30f;
                if (c0 > r1) s[nt][2] = -1e30f;
                if (c1 > r1) s[nt][3] = -1e30f;
            }
            tm0 = fmaxf(tm0, fmaxf(s[nt][0], s[nt][1]));
            tm1 = fmaxf(tm1, fmaxf(s[nt][2], s[nt][3]));
        }
        tm0 = fmaxf(tm0, __shfl_xor_sync(0xffffffffu, tm0, 1));
        tm0 = fmaxf(tm0, __shfl_xor_sync(0xffffffffu, tm0, 2));
        tm1 = fmaxf(tm1, __shfl_xor_sync(0xffffffffu, tm1, 1));
        tm1 = fmaxf(tm1, __shfl_xor_sync(0xffffffffu, tm1, 2));

        const float mn0 = fmaxf(m0, tm0), mn1 = fmaxf(m1, tm1);
        const float corr0 = ex2(m0 - mn0), corr1 = ex2(m1 - mn1);
        m0 = mn0; m1 = mn1;

        float rs0 = 0.f, rs1 = 0.f;
        unsigned pf[4][4];
#pragma unroll
        for (int tp = 0; tp < 4; tp++) {
            float* e0 = s[2 * tp];
            float* e1 = s[2 * tp + 1];
            e0[0] = ex2(e0[0] - mn0); e0[1] = ex2(e0[1] - mn0);
            e0[2] = ex2(e0[2] - mn1); e0[3] = ex2(e0[3] - mn1);
            e1[0] = ex2(e1[0] - mn0); e1[1] = ex2(e1[1] - mn0);
            e1[2] = ex2(e1[2] - mn1); e1[3] = ex2(e1[3] - mn1);
            rs0 += e0[0] + e0[1] + e1[0] + e1[1];
            rs1 += e0[2] + e0[3] + e1[2] + e1[3];
            pf[tp][0] = h2u(e0[0], e0[1]);
            pf[tp][1] = h2u(e0[2], e0[3]);
            pf[tp][2] = h2u(e1[0], e1[1]);
            pf[tp][3] = h2u(e1[2], e1[3]);
        }
        rs0 += __shfl_xor_sync(0xffffffffu, rs0, 1);
        rs0 += __shfl_xor_sync(0xffffffffu, rs0, 2);
        rs1 += __shfl_xor_sync(0xffffffffu, rs1, 1);
        rs1 += __shfl_xor_sync(0xffffffffu, rs1, 2);
        l0 = l0 * corr0 + rs0;
        l1 = l1 * corr1 + rs1;
#pragma unroll
        for (int nt = 0; nt < 8; nt++) {
            o[nt][0] *= corr0; o[nt][1] *= corr0;
            o[nt][2] *= corr1; o[nt][3] *= corr1;
        }

        // O += P V
#pragma unroll
        for (int ts = 0; ts < 4; ts++) {
#pragma unroll
            for (int ep = 0; ep < 4; ep++) {
                unsigned b0, b1, b2, b3;
                ldsm4t(b0, b1, b2, b3,
                       Kc + (ts * 16 + tv_row) * KST + ep * 16 + tv_col);
                mma_f16(o[2*ep][0], o[2*ep][1], o[2*ep][2], o[2*ep][3],
                        pf[ts][0], pf[ts][1], pf[ts][2], pf[ts][3], b0, b1);
                mma_f16(o[2*ep+1][0], o[2*ep+1][1], o[2*ep+1][2], o[2*ep+1][3],
                        pf[ts][0], pf[ts][1], pf[ts][2], pf[ts][3], b2, b3);
            }
        }
    };

    if (CAUSAL) {
        for (int t = 0; t < nTiles - 2; t++) tile_body(t, false);
        tile_body(nTiles - 2, true);
        tile_body(nTiles - 1, true);
    } else {
        for (int t = 0; t < nTiles; t++) tile_body(t, false);
    }

    const float inv0 = 1.f / l0, inv1 = 1.f / l1;
    float* Oh = O + (long long)(rowBlk * 128) * DD + h * DHD;
#pragma unroll
    for (int nt = 0; nt < 8; nt++) {
        const int c = nt * 8 + 2 * tig;
        *(float2*)&Oh[(long long)(mr + g)     * DD + c] =
            make_float2(o[nt][0] * inv0, o[nt][1] * inv0);
        *(float2*)&Oh[(long long)(mr + g + 8) * DD + c] =
            make_float2(o[nt][2] * inv1, o[nt][3] * inv1);
    }
}

// ---------------- add + LayerNorm (float4) -----------------------------------
__global__ __launch_bounds__(256)
void add_ln_kernel(const float* __restrict__ a, const float* __restrict__ b,
                   const float* __restrict__ gamma, const float* __restrict__ beta,
                   float* __restrict__ out, __half* __restrict__ hout)
{
    const int row = blockIdx.x;
    const int tid = threadIdx.x;
    const float4* pa = (const float4*)(a + (long long)row * DD);
    const float4* pb = (const float4*)(b + (long long)row * DD);
    __shared__ float red[256];

    float4 v = pa[tid], w = pb[tid];
    v.x += w.x; v.y += w.y; v.z += w.z; v.w += w.w;
    red[tid] = v.x + v.y + v.z + v.w; __syncthreads();
    for (int o = 128; o; o >>= 1) { if (tid < o) red[tid] += red[tid + o]; __syncthreads(); }
    const float mu = red[0] * (1.f / DD); __syncthreads();

    float var = (v.x - mu) * (v.x - mu) + (v.y - mu) * (v.y - mu)
              + (v.z - mu) * (v.z - mu) + (v.w - mu) * (v.w - mu);
    red[tid] = var; __syncthreads();
    for (int o = 128; o; o >>= 1) { if (tid < o) red[tid] += red[tid + o]; __syncthreads(); }
    const float rs = rsqrtf(red[0] * (1.f / DD) + 1e-5f); __syncthreads();

    const float4 gm = ((const float4*)gamma)[tid];
    const float4 bt = ((const float4*)beta)[tid];
    float4 ov;
    ov.x = (v.x - mu) * rs * gm.x + bt.x;
    ov.y = (v.y - mu) * rs * gm.y + bt.y;
    ov.z = (v.z - mu) * rs * gm.z + bt.z;
    ov.w = (v.w - mu) * rs * gm.w + bt.w;
    if (out) ((float4*)(out + (long long)row * DD))[tid] = ov;
    if (hout) {
        __half2* hp = (__half2*)(hout + (long long)row * DD);
        hp[2 * tid]     = __floats2half2_rn(ov.x, ov.y);
        hp[2 * tid + 1] = __floats2half2_rn(ov.z, ov.w);
    }
}

// ---------------- orchestration ----------------------------------------------
extern "C" void kernel_launch(void* const* d_in, const int* in_sizes, int n_in,
                              void* d_out, int out_size)
{
    const float* y    = (const float*)d_in[0];
    const float* enc  = (const float*)d_in[1];
    const float* Wqs  = (const float*)d_in[2];
    const float* bqs  = (const float*)d_in[3];
    const float* Wqc  = (const float*)d_in[4];
    const float* bqc  = (const float*)d_in[5];
    const float* g1   = (const float*)d_in[6];
    const float* be1  = (const float*)d_in[7];
    const float* g2   = (const float*)d_in[8];
    const float* be2  = (const float*)d_in[9];
    const float* g3   = (const float*)d_in[10];
    const float* be3  = (const float*)d_in[11];
    const float* w1   = (const float*)d_in[12];
    const float* b1   = (const float*)d_in[13];
    const float* w2   = (const float*)d_in[14];
    const float* b2   = (const float*)d_in[15];
    float* out = (float*)d_out;

    float *tmp, *y1, *y2;
    __half *qh, *qch, *kch, *yh, *y1h, *y2h, *ench, *wqst, *wqct, *w1t, *w2t, *hidh;
    cudaGetSymbolAddress((void**)&tmp,  g_tmp);
    cudaGetSymbolAddress((void**)&y1,   g_y1);
    cudaGetSymbolAddress((void**)&y2,   g_y2);
    cudaGetSymbolAddress((void**)&qh,   g_qh);
    cudaGetSymbolAddress((void**)&qch,  g_qch);
    cudaGetSymbolAddress((void**)&kch,  g_kch);
    cudaGetSymbolAddress((void**)&yh,   g_yh);
    cudaGetSymbolAddress((void**)&y1h,  g_y1h);
    cudaGetSymbolAddress((void**)&y2h,  g_y2h);
    cudaGetSymbolAddress((void**)&ench, g_ench);
    cudaGetSymbolAddress((void**)&wqst, g_wqst);
    cudaGetSymbolAddress((void**)&wqct, g_wqct);
    cudaGetSymbolAddress((void**)&w1t,  g_w1t);
    cudaGetSymbolAddress((void**)&w2t,  g_w2t);
    cudaGetSymbolAddress((void**)&hidh, g_hidh);

    const long long WST = (long long)DHD * DD;
    const long long QST = (long long)SS * DHD;

    const int GS64  = 3 * (BM + 64)  * SAH * 2;
    const int GS128 = 3 * (BM + 128) * SAH * 2;
    const int FSMEM = (2 * 64 + 128) * KST * 2;

    cudaFuncSetAttribute(gemm_h<64>,
                         cudaFuncAttributeMaxDynamicSharedMemorySize, GS64);
    cudaFuncSetAttribute(gemm_h<128>,
                         cudaFuncAttributeMaxDynamicSharedMemorySize, GS128);
    cudaFuncSetAttribute(flash_h<true>,
                         cudaFuncAttributeMaxDynamicSharedMemorySize, FSMEM);
    cudaFuncSetAttribute(flash_h<false>,
                         cudaFuncAttributeMaxDynamicSharedMemorySize, FSMEM);

    // ---- conversions ----
    f2h2_kernel<<<592, 256>>>(y, yh, enc, ench, SS * DD / 4);
    conv_trans_kernel<<<dim3(DHD / 32, DD / 32, 2 * HH), dim3(32, 8)>>>(
        Wqs, wqst, Wqc, wqct, DD, DHD, HH);
    conv_trans_kernel<<<dim3(HID / 32, DD / 32, 1), dim3(32, 8)>>>(
        w1, w1t, nullptr, nullptr, DD, HID, 1);
    conv_trans_kernel<<<dim3(DD / 32, HID / 32, 1), dim3(32, 8)>>>(
        w2, w2t, nullptr, nullptr, HID, DD, 1);

    // ---- self attention (q = k = v) ----
    gemm_h<64><<<dim3(1, SS / BM, HH), 256, GS64>>>(
        yh, wqst, bqs, nullptr, qh, nullptr, nullptr,
        DD, DD, DD, DHD, 0, WST, DHD, QST, 0);
    flash_h<true><<<dim3(SS / 128, HH), 256, FSMEM>>>(qh, qh, tmp);
    add_ln_kernel<<<SS, 256>>>(y, tmp, g1, be1, y1, y1h);

    // ---- cross attention (k = v): q and k projections in ONE launch ----
    gemm_h<64><<<dim3(1, SS / BM, 2 * HH), 256, GS64>>>(
        y1h, wqct, bqc, nullptr, qch, ench, kch,
        DD, DD, DD, DHD, 0, WST, DHD, QST, 0);
    flash_h<false><<<dim3(SS / 128, HH), 256, FSMEM>>>(qch, kch, tmp);
    add_ln_kernel<<<SS, 256>>>(y1, tmp, g2, be2, y2, y2h);

    // ---- FFN ----
    gemm_h<128><<<dim3(HID / 128, SS / BM, 1), 256, GS128>>>(
        y2h, w1t, b1, nullptr, hidh, nullptr, nullptr,
        DD, DD, DD, HID, 0, 0, 0, 0, 1);
    gemm_h<64><<<dim3(DD / 64, SS / BM, 1), 256, GS64>>>(
        hidh, w2t, b2, tmp, nullptr, nullptr, nullptr,
        HID, HID, HID, DD, 0, 0, 0, 0, 0);
    add_ln_kernel<<<SS, 256>>>(y2, tmp, g3, be3, out, nullptr);
}

// round 13
// speedup vs baseline: 2.3034x; 1.0463x over previous
#include <cuda_runtime.h>
#include <cuda_fp16.h>
#include <math.h>

#define HH  16
#define SS  2048
#define DD  1024
#define DHD 64
#define HID 4096

// ---------------- scratch ----------------------------------------------------
__device__ float g_tmp [SS * DD];
__device__ float g_y1  [SS * DD];
__device__ float g_y2  [SS * DD];
// q/k buffers in per-head [h][s][e] layout (round-11 flash layout)
__device__ __align__(16) __half g_qh  [HH * SS * DHD];
__device__ __align__(16) __half g_qch [HH * SS * DHD];
__device__ __align__(16) __half g_kch [HH * SS * DHD];
__device__ __align__(16) __half g_yh  [SS * DD];
__device__ __align__(16) __half g_y1h [SS * DD];
__device__ __align__(16) __half g_y2h [SS * DD];
__device__ __align__(16) __half g_ench[SS * DD];
__device__ __align__(16) __half g_wqst[DD * DD];     // flat [h*64+n][k]
__device__ __align__(16) __half g_wqct[DD * DD];
__device__ __align__(16) __half g_w1t [HID * DD];
__device__ __align__(16) __half g_w2t [DD * HID];
__device__ __align__(16) __half g_hidh[SS * HID];

// ---------------- helpers ----------------------------------------------------
__device__ __forceinline__ void mma_f16(
    float& d0, float& d1, float& d2, float& d3,
    unsigned a0, unsigned a1, unsigned a2, unsigned a3,
    unsigned b0, unsigned b1)
{
    asm volatile(
        "mma.sync.aligned.m16n8k16.row.col.f32.f16.f16.f32 "
        "{%0,%1,%2,%3}, {%4,%5,%6,%7}, {%8,%9}, {%0,%1,%2,%3};"
        : "+f"(d0), "+f"(d1), "+f"(d2), "+f"(d3)
        : "r"(a0), "r"(a1), "r"(a2), "r"(a3), "r"(b0), "r"(b1));
}
__device__ __forceinline__ void cp16h(__half* dst, const __half* src) {
    unsigned d = (unsigned)__cvta_generic_to_shared(dst);
    asm volatile("cp.async.cg.shared.global [%0], [%1], 16;" :: "r"(d), "l"(src));
}
#define CP_COMMIT() asm volatile("cp.async.commit_group;")
#define CP_WAIT1()  asm volatile("cp.async.wait_group 1;")
#define CP_WAIT0()  asm volatile("cp.async.wait_group 0;")

__device__ __forceinline__ void ldsm4h(unsigned& r0, unsigned& r1,
                                       unsigned& r2, unsigned& r3, const __half* p)
{
    unsigned a = (unsigned)__cvta_generic_to_shared(p);
    asm volatile("ldmatrix.sync.aligned.m8n8.x4.shared.b16 {%0,%1,%2,%3}, [%4];"
                 : "=r"(r0), "=r"(r1), "=r"(r2), "=r"(r3) : "r"(a));
}
__device__ __forceinline__ void ldsm4t(unsigned& r0, unsigned& r1,
                                       unsigned& r2, unsigned& r3, const __half* p)
{
    unsigned a = (unsigned)__cvta_generic_to_shared(p);
    asm volatile("ldmatrix.sync.aligned.m8n8.x4.trans.shared.b16 {%0,%1,%2,%3}, [%4];"
                 : "=r"(r0), "=r"(r1), "=r"(r2), "=r"(r3) : "r"(a));
}
__device__ __forceinline__ unsigned h2u(float a, float b) {
    __half2 h = __floats2half2_rn(a, b);
    return *(unsigned*)&h;
}
__device__ __forceinline__ float ex2(float x) {
    float y; asm("ex2.approx.ftz.f32 %0, %1;" : "=f"(y) : "f"(x)); return y;
}

// ---------------- conversion kernels -----------------------------------------
__global__ __launch_bounds__(256)
void f2h2_kernel(const float* __restrict__ in0, __half* __restrict__ out0,
                 const float* __restrict__ in1, __half* __restrict__ out1, int n4)
{
    for (int i = blockIdx.x * 256 + threadIdx.x; i < 2 * n4; i += gridDim.x * 256) {
        const float* in = (i < n4) ? in0 : in1;
        __half* out = (i < n4) ? out0 : out1;
        const int j = (i < n4) ? i : i - n4;
        float4 v = ((const float4*)in)[j];
        ((__half2*)out)[2 * j]     = __floats2half2_rn(v.x, v.y);
        ((__half2*)out)[2 * j + 1] = __floats2half2_rn(v.z, v.w);
    }
}

__global__ void conv_trans_kernel(const float* __restrict__ in0, __half* __restrict__ out0,
                                  const float* __restrict__ in1, __half* __restrict__ out1,
                                  int R, int C, int zsplit)
{
    __shared__ float t[32][33];
    int z = blockIdx.z;
    const float* in = in0; __half* out = out0;
    if (in1 && z >= zsplit) { in = in1; out = out1; z -= zsplit; }
    const long long bo = (long long)z * R * C;
    in += bo; out += bo;
    const int c0 = blockIdx.x * 32, r0 = blockIdx.y * 32;
    const int tx = threadIdx.x, ty = threadIdx.y;
#pragma unroll
    for (int i = 0; i < 4; i++)
        t[ty + 8 * i][tx] = in[(long long)(r0 + ty + 8 * i) * C + c0 + tx];
    __syncthreads();
#pragma unroll
    for (int i = 0; i < 4; i++)
        out[(long long)(c0 + ty + 8 * i) * R + r0 + tx] = __float2half(t[tx][ty + 8 * i]);
}

// ======================= fp16 tensor-core GEMM (BK=64) ======================
// A [M][K] half, B [N][K] half. Optional A2/Ch2 for z >= zsplit.
// headSplit: scatter Ch output to per-head layout [cc>>6][row][cc&63].
#define BM 128
#define BK 64
#define SAH 72

template<int BN>
__global__ __launch_bounds__(256)
void gemm_h(const __half* __restrict__ A, const __half* __restrict__ B,
            const float* __restrict__ bias, float* __restrict__ C,
            __half* __restrict__ Ch,
            const __half* __restrict__ A2, __half* __restrict__ Ch2, int zsplit,
            int K, int lda, int ldb, int ldc,
            int headSplit, int relu)
{
    constexpr int NTT  = BN / 16;
    constexpr int ABUF = BM * SAH;
    constexpr int BBUF = BN * SAH;
    constexpr int BPASS = BN / 32;

    extern __shared__ __half smh[];
    __half* As = smh;
    __half* Bs = smh + 3 * ABUF;

    if (A2 && (int)blockIdx.z >= zsplit) { A = A2; Ch = Ch2; }

    const int rowStart = blockIdx.y * BM;
    const int colStart = blockIdx.x * BN;
    const int nK = K / BK;

    const int tid  = threadIdx.x;
    const int wid  = tid >> 5, lane = tid & 31;
    const int g    = lane >> 2, tig = lane & 3;
    const int warpM = wid & 3, warpN = wid >> 2;

    const int a_r = tid >> 3, a_c = (tid & 7) << 3;
    const __half* Agp = A + (long long)(rowStart + a_r) * lda + a_c;
    const __half* Bgp = B + (long long)(colStart + a_r) * ldb + a_c;

    const int am_row = lane & 15;
    const int am_col = (lane & 16) ? 8 : 0;
    const int bn_row = (lane & 7) + ((lane & 16) ? 8 : 0);
    const int bn_col = lane & 8;

    auto issue = [&](int kt) {
        const int k0 = kt * BK;
        __half* Ad = As + (kt % 3) * ABUF;
        __half* Bd = Bs + (kt % 3) * BBUF;
#pragma unroll
        for (int i = 0; i < 4; i++)
            cp16h(Ad + (a_r + 32 * i) * SAH + a_c, Agp + (long long)(32 * i) * lda + k0);
#pragma unroll
        for (int i = 0; i < BPASS; i++)
            cp16h(Bd + (a_r + 32 * i) * SAH + a_c, Bgp + (long long)(32 * i) * ldb + k0);
        CP_COMMIT();
    };

    float acc[2][NTT][4];
#pragma unroll
    for (int mt = 0; mt < 2; mt++)
#pragma unroll
        for (int nt = 0; nt < NTT; nt++)
#pragma unroll
            for (int i = 0; i < 4; i++) acc[mt][nt][i] = 0.f;

    issue(0);
    if (nK > 1) issue(1);

    for (int kt = 0; kt < nK; kt++) {
        CP_WAIT1();
        __syncthreads();
        if (kt + 2 < nK) issue(kt + 2);

        const __half* Ac = As + (kt % 3) * ABUF;
        const __half* Bc = Bs + (kt % 3) * BBUF;
#pragma unroll
        for (int ks = 0; ks < 4; ks++) {
            const int ko = ks * 16;
            unsigned af[2][4];
#pragma unroll
            for (int mt = 0; mt < 2; mt++)
                ldsm4h(af[mt][0], af[mt][1], af[mt][2], af[mt][3],
                       Ac + (warpM * 32 + mt * 16 + am_row) * SAH + ko + am_col);
            unsigned bf[NTT][2];
#pragma unroll
            for (int np = 0; np < NTT / 2; np++) {
                const int nb = warpN * (BN / 2) + np * 16;
                unsigned r0, r1, r2, r3;
                ldsm4h(r0, r1, r2, r3, Bc + (nb + bn_row) * SAH + ko + bn_col);
                bf[2 * np][0] = r0;     bf[2 * np][1] = r1;
                bf[2 * np + 1][0] = r2; bf[2 * np + 1][1] = r3;
            }
#pragma unroll
            for (int mt = 0; mt < 2; mt++)
#pragma unroll
                for (int nt = 0; nt < NTT; nt++)
                    mma_f16(acc[mt][nt][0], acc[mt][nt][1], acc[mt][nt][2], acc[mt][nt][3],
                            af[mt][0], af[mt][1], af[mt][2], af[mt][3],
                            bf[nt][0], bf[nt][1]);
        }
    }

#pragma unroll
    for (int mt = 0; mt < 2; mt++) {
        const int r = rowStart + warpM * 32 + mt * 16 + g;
#pragma unroll
        for (int nt = 0; nt < NTT; nt++) {
            const int cc = colStart + warpN * (BN / 2) + nt * 8 + 2 * tig;
            const float bb0 = bias ? bias[cc]     : 0.f;
            const float bb1 = bias ? bias[cc + 1] : 0.f;
            float v0 = acc[mt][nt][0] + bb0;
            float v1 = acc[mt][nt][1] + bb1;
            float v2 = acc[mt][nt][2] + bb0;
            float v3 = acc[mt][nt][3] + bb1;
            if (relu) { v0 = fmaxf(v0, 0.f); v1 = fmaxf(v1, 0.f);
                        v2 = fmaxf(v2, 0.f); v3 = fmaxf(v3, 0.f); }
            if (headSplit) {
                // per-head layout: [head][row][e]; pairs stay within a head
                const long long ro =
                    ((long long)(cc >> 6) * SS + r) * DHD + (cc & 63);
                *(__half2*)&Ch[ro]             = __floats2half2_rn(v0, v1);
                *(__half2*)&Ch[ro + 8 * DHD]   = __floats2half2_rn(v2, v3);
            } else if (Ch) {
                *(__half2*)&Ch[(long long)r       * ldc + cc] = __floats2half2_rn(v0, v1);
                *(__half2*)&Ch[(long long)(r + 8) * ldc + cc] = __floats2half2_rn(v2, v3);
            } else {
                *(float2*)&C[(long long)r       * ldc + cc] = make_float2(v0, v1);
                *(float2*)&C[(long long)(r + 8) * ldc + cc] = make_float2(v2, v3);
            }
        }
    }
}

// ======================= fp16 flash attention (round-11, per-head layout) ===
#define KST 72
#define SM_SCALE2 0.18033688f

template<bool CAUSAL>
__global__ __launch_bounds__(256)
void flash_h(const __half* __restrict__ Q, const __half* __restrict__ KV,
             float* __restrict__ O)
{
    extern __shared__ __half smh[];
    __half* Ks = smh;                   // 2 * 64 * KST
    __half* Qs = smh + 2 * 64 * KST;    // 128 * KST

    const int h = blockIdx.y;
    const int rowBlk = CAUSAL ? (gridDim.x - 1 - blockIdx.x) : blockIdx.x;
    const __half* Qh = Q  + (long long)h * SS * DHD + (long long)rowBlk * 128 * DHD;
    const __half* Kh = KV + (long long)h * SS * DHD;

    const int tid = threadIdx.x, wid = tid >> 5, lane = tid & 31;
    const int g = lane >> 2, tig = lane & 3;
    const int mr = wid * 16;

    const int am_row = lane & 15;
    const int am_col = (lane & 16) ? 8 : 0;
    const int bn_row = (lane & 7) + ((lane & 16) ? 8 : 0);
    const int bn_col = lane & 8;
    const int tv_row = (lane & 7) + (lane & 8);
    const int tv_col = (lane & 16) ? 8 : 0;

    const int k_r = tid >> 3, k_c = (tid & 7) << 3;

    auto issueK = [&](int t) {
        __half* Kd = Ks + (t & 1) * 64 * KST;
        const __half* src = Kh + (long long)(t * 64 + k_r) * DHD + k_c;
        cp16h(Kd + k_r * KST + k_c, src);
        cp16h(Kd + (k_r + 32) * KST + k_c, src + 32 * DHD);
        CP_COMMIT();
    };

    for (int i = tid; i < 128 * 8; i += 256) {
        const int r = i >> 3, c8 = (i & 7) << 3;
        *(uint4*)&Qs[r * KST + c8] = *(const uint4*)(Qh + (long long)r * DHD + c8);
    }
    issueK(0);
    __syncthreads();
    unsigned qf[4][4];
#pragma unroll
    for (int ks = 0; ks < 4; ks++)
        ldsm4h(qf[ks][0], qf[ks][1], qf[ks][2], qf[ks][3],
               Qs + (mr + am_row) * KST + ks * 16 + am_col);

    float o[8][4];
#pragma unroll
    for (int nt = 0; nt < 8; nt++)
#pragma unroll
        for (int i = 0; i < 4; i++) o[nt][i] = 0.f;
    float m0 = -1e30f, m1 = -1e30f, l0 = 0.f, l1 = 0.f;

    const int nTiles = CAUSAL ? 2 * (rowBlk + 1) : SS / 64;
    const int r0 = rowBlk * 128 + mr + g;
    const int r1 = r0 + 8;

    auto tile_body = [&](int t, bool MASKED) {
        CP_WAIT0();
        __syncthreads();
        if (t + 1 < nTiles) issueK(t + 1);
        const __half* Kc = Ks + (t & 1) * 64 * KST;

        float s[8][4];
#pragma unroll
        for (int nt = 0; nt < 8; nt++) { s[nt][0] = s[nt][1] = s[nt][2] = s[nt][3] = 0.f; }
#pragma unroll
        for (int ks = 0; ks < 4; ks++) {
#pragma unroll
            for (int tp = 0; tp < 4; tp++) {
                unsigned b0, b1, b2, b3;
                ldsm4h(b0, b1, b2, b3,
                       Kc + (tp * 16 + bn_row) * KST + ks * 16 + bn_col);
                mma_f16(s[2*tp][0], s[2*tp][1], s[2*tp][2], s[2*tp][3],
                        qf[ks][0], qf[ks][1], qf[ks][2], qf[ks][3], b0, b1);
                mma_f16(s[2*tp+1][0], s[2*tp+1][1], s[2*tp+1][2], s[2*tp+1][3],
                        qf[ks][0], qf[ks][1], qf[ks][2], qf[ks][3], b2, b3);
            }
        }

        const int cb = t * 64;
        float tm0 = -1e30f, tm1 = -1e30f;
#pragma unroll
        for (int nt = 0; nt < 8; nt++) {
            s[nt][0] *= SM_SCALE2; s[nt][1] *= SM_SCALE2;
            s[nt][2] *= SM_SCALE2; s[nt][3] *= SM_SCALE2;
            if (MASKED) {
                const int c0 = cb + nt * 8 + 2 * tig, c1 = c0 + 1;
                if (c0 > r0) s[nt][0] = -1e30f;
                if (c1 > r0) s[nt][1] = -1e30f;
                if (c0 > r1) s[nt][2] = -1e30f;
                if (c1 > r1) s[nt][3] = -1e30f;
            }
            tm0 = fmaxf(tm0, fmaxf(s[nt][0], s[nt][1]));
            tm1 = fmaxf(tm1, fmaxf(s[nt][2], s[nt][3]));
        }
        tm0 = fmaxf(tm0, __shfl_xor_sync(0xffffffffu, tm0, 1));
        tm0 = fmaxf(tm0, __shfl_xor_sync(0xffffffffu, tm0, 2));
        tm1 = fmaxf(tm1, __shfl_xor_sync(0xffffffffu, tm1, 1));
        tm1 = fmaxf(tm1, __shfl_xor_sync(0xffffffffu, tm1, 2));

        const float mn0 = fmaxf(m0, tm0), mn1 = fmaxf(m1, tm1);
        const float corr0 = ex2(m0 - mn0), corr1 = ex2(m1 - mn1);
        m0 = mn0; m1 = mn1;

        float rs0 = 0.f, rs1 = 0.f;
        unsigned pf[4][4];
#pragma unroll
        for (int tp = 0; tp < 4; tp++) {
            float* e0 = s[2 * tp];
            float* e1 = s[2 * tp + 1];
            e0[0] = ex2(e0[0] - mn0); e0[1] = ex2(e0[1] - mn0);
            e0[2] = ex2(e0[2] - mn1); e0[3] = ex2(e0[3] - mn1);
            e1[0] = ex2(e1[0] - mn0); e1[1] = ex2(e1[1] - mn0);
            e1[2] = ex2(e1[2] - mn1); e1[3] = ex2(e1[3] - mn1);
            rs0 += e0[0] + e0[1] + e1[0] + e1[1];
            rs1 += e0[2] + e0[3] + e1[2] + e1[3];
            pf[tp][0] = h2u(e0[0], e0[1]);
            pf[tp][1] = h2u(e0[2], e0[3]);
            pf[tp][2] = h2u(e1[0], e1[1]);
            pf[tp][3] = h2u(e1[2], e1[3]);
        }
        rs0 += __shfl_xor_sync(0xffffffffu, rs0, 1);
        rs0 += __shfl_xor_sync(0xffffffffu, rs0, 2);
        rs1 += __shfl_xor_sync(0xffffffffu, rs1, 1);
        rs1 += __shfl_xor_sync(0xffffffffu, rs1, 2);
        l0 = l0 * corr0 + rs0;
        l1 = l1 * corr1 + rs1;
#pragma unroll
        for (int nt = 0; nt < 8; nt++) {
            o[nt][0] *= corr0; o[nt][1] *= corr0;
            o[nt][2] *= corr1; o[nt][3] *= corr1;
        }

#pragma unroll
        for (int ts = 0; ts < 4; ts++) {
#pragma unroll
            for (int ep = 0; ep < 4; ep++) {
                unsigned b0, b1, b2, b3;
                ldsm4t(b0, b1, b2, b3,
                       Kc + (ts * 16 + tv_row) * KST + ep * 16 + tv_col);
                mma_f16(o[2*ep][0], o[2*ep][1], o[2*ep][2], o[2*ep][3],
                        pf[ts][0], pf[ts][1], pf[ts][2], pf[ts][3], b0, b1);
                mma_f16(o[2*ep+1][0], o[2*ep+1][1], o[2*ep+1][2], o[2*ep+1][3],
                        pf[ts][0], pf[ts][1], pf[ts][2], pf[ts][3], b2, b3);
            }
        }
    };

    if (CAUSAL) {
        for (int t = 0; t < nTiles - 2; t++) tile_body(t, false);
        tile_body(nTiles - 2, true);
        tile_body(nTiles - 1, true);
    } else {
        for (int t = 0; t < nTiles; t++) tile_body(t, false);
    }

    const float inv0 = 1.f / l0, inv1 = 1.f / l1;
    float* Oh = O + (long long)(rowBlk * 128) * DD + h * DHD;
#pragma unroll
    for (int nt = 0; nt < 8; nt++) {
        const int c = nt * 8 + 2 * tig;
        *(float2*)&Oh[(long long)(mr + g)     * DD + c] =
            make_float2(o[nt][0] * inv0, o[nt][1] * inv0);
        *(float2*)&Oh[(long long)(mr + g + 8) * DD + c] =
            make_float2(o[nt][2] * inv1, o[nt][3] * inv1);
    }
}

// ---------------- add + LayerNorm (float4) -----------------------------------
__global__ __launch_bounds__(256)
void add_ln_kernel(const float* __restrict__ a, const float* __restrict__ b,
                   const float* __restrict__ gamma, const float* __restrict__ beta,
                   float* __restrict__ out, __half* __restrict__ hout)
{
    const int row = blockIdx.x;
    const int tid = threadIdx.x;
    const float4* pa = (const float4*)(a + (long long)row * DD);
    const float4* pb = (const float4*)(b + (long long)row * DD);
    __shared__ float red[256];

    float4 v = pa[tid], w = pb[tid];
    v.x += w.x; v.y += w.y; v.z += w.z; v.w += w.w;
    red[tid] = v.x + v.y + v.z + v.w; __syncthreads();
    for (int o = 128; o; o >>= 1) { if (tid < o) red[tid] += red[tid + o]; __syncthreads(); }
    const float mu = red[0] * (1.f / DD); __syncthreads();

    float var = (v.x - mu) * (v.x - mu) + (v.y - mu) * (v.y - mu)
              + (v.z - mu) * (v.z - mu) + (v.w - mu) * (v.w - mu);
    red[tid] = var; __syncthreads();
    for (int o = 128; o; o >>= 1) { if (tid < o) red[tid] += red[tid + o]; __syncthreads(); }
    const float rs = rsqrtf(red[0] * (1.f / DD) + 1e-5f); __syncthreads();

    const float4 gm = ((const float4*)gamma)[tid];
    const float4 bt = ((const float4*)beta)[tid];
    float4 ov;
    ov.x = (v.x - mu) * rs * gm.x + bt.x;
    ov.y = (v.y - mu) * rs * gm.y + bt.y;
    ov.z = (v.z - mu) * rs * gm.z + bt.z;
    ov.w = (v.w - mu) * rs * gm.w + bt.w;
    if (out) ((float4*)(out + (long long)row * DD))[tid] = ov;
    if (hout) {
        __half2* hp = (__half2*)(hout + (long long)row * DD);
        hp[2 * tid]     = __floats2half2_rn(ov.x, ov.y);
        hp[2 * tid + 1] = __floats2half2_rn(ov.z, ov.w);
    }
}

// ---------------- orchestration ----------------------------------------------
extern "C" void kernel_launch(void* const* d_in, const int* in_sizes, int n_in,
                              void* d_out, int out_size)
{
    const float* y    = (const float*)d_in[0];
    const float* enc  = (const float*)d_in[1];
    const float* Wqs  = (const float*)d_in[2];
    const float* bqs  = (const float*)d_in[3];
    const float* Wqc  = (const float*)d_in[4];
    const float* bqc  = (const float*)d_in[5];
    const float* g1   = (const float*)d_in[6];
    const float* be1  = (const float*)d_in[7];
    const float* g2   = (const float*)d_in[8];
    const float* be2  = (const float*)d_in[9];
    const float* g3   = (const float*)d_in[10];
    const float* be3  = (const float*)d_in[11];
    const float* w1   = (const float*)d_in[12];
    const float* b1   = (const float*)d_in[13];
    const float* w2   = (const float*)d_in[14];
    const float* b2   = (const float*)d_in[15];
    float* out = (float*)d_out;

    float *tmp, *y1, *y2;
    __half *qh, *qch, *kch, *yh, *y1h, *y2h, *ench, *wqst, *wqct, *w1t, *w2t, *hidh;
    cudaGetSymbolAddress((void**)&tmp,  g_tmp);
    cudaGetSymbolAddress((void**)&y1,   g_y1);
    cudaGetSymbolAddress((void**)&y2,   g_y2);
    cudaGetSymbolAddress((void**)&qh,   g_qh);
    cudaGetSymbolAddress((void**)&qch,  g_qch);
    cudaGetSymbolAddress((void**)&kch,  g_kch);
    cudaGetSymbolAddress((void**)&yh,   g_yh);
    cudaGetSymbolAddress((void**)&y1h,  g_y1h);
    cudaGetSymbolAddress((void**)&y2h,  g_y2h);
    cudaGetSymbolAddress((void**)&ench, g_ench);
    cudaGetSymbolAddress((void**)&wqst, g_wqst);
    cudaGetSymbolAddress((void**)&wqct, g_wqct);
    cudaGetSymbolAddress((void**)&w1t,  g_w1t);
    cudaGetSymbolAddress((void**)&w2t,  g_w2t);
    cudaGetSymbolAddress((void**)&hidh, g_hidh);

    const int GS64  = 3 * (BM + 64)  * SAH * 2;
    const int GS128 = 3 * (BM + 128) * SAH * 2;
    const int FSMEM = (2 * 64 + 128) * KST * 2;

    cudaFuncSetAttribute(gemm_h<64>,
                         cudaFuncAttributeMaxDynamicSharedMemorySize, GS64);
    cudaFuncSetAttribute(gemm_h<128>,
                         cudaFuncAttributeMaxDynamicSharedMemorySize, GS128);
    cudaFuncSetAttribute(flash_h<true>,
                         cudaFuncAttributeMaxDynamicSharedMemorySize, FSMEM);
    cudaFuncSetAttribute(flash_h<false>,
                         cudaFuncAttributeMaxDynamicSharedMemorySize, FSMEM);

    // ---- conversions ----
    f2h2_kernel<<<592, 256>>>(y, yh, enc, ench, SS * DD / 4);
    conv_trans_kernel<<<dim3(DHD / 32, DD / 32, 2 * HH), dim3(32, 8)>>>(
        Wqs, wqst, Wqc, wqct, DD, DHD, HH);
    conv_trans_kernel<<<dim3(HID / 32, DD / 32, 1), dim3(32, 8)>>>(
        w1, w1t, nullptr, nullptr, DD, HID, 1);
    conv_trans_kernel<<<dim3(DD / 32, HID / 32, 1), dim3(32, 8)>>>(
        w2, w2t, nullptr, nullptr, HID, DD, 1);

    // ---- self attention (q = k = v): full-width GEMM, per-head output ----
    gemm_h<128><<<dim3(DD / 128, SS / BM, 1), 256, GS128>>>(
        yh, wqst, bqs, nullptr, qh, nullptr, nullptr, 0,
        DD, DD, DD, DD, 1, 0);
    flash_h<true><<<dim3(SS / 128, HH), 256, FSMEM>>>(qh, qh, tmp);
    add_ln_kernel<<<SS, 256>>>(y, tmp, g1, be1, y1, y1h);

    // ---- cross attention: fused q+k full-width, per-head output ----
    gemm_h<128><<<dim3(DD / 128, SS / BM, 2), 256, GS128>>>(
        y1h, wqct, bqc, nullptr, qch, ench, kch, 1,
        DD, DD, DD, DD, 1, 0);
    flash_h<false><<<dim3(SS / 128, HH), 256, FSMEM>>>(qch, kch, tmp);
    add_ln_kernel<<<SS, 256>>>(y1, tmp, g2, be2, y2, y2h);

    // ---- FFN ----
    gemm_h<128><<<dim3(HID / 128, SS / BM, 1), 256, GS128>>>(
        y2h, w1t, b1, nullptr, hidh, nullptr, nullptr, 0,
        DD, DD, DD, HID, 0, 1);
    gemm_h<64><<<dim3(DD / 64, SS / BM, 1), 256, GS64>>>(
        hidh, w2t, b2, tmp, nullptr, nullptr, nullptr, 0,
        HID, HID, HID, DD, 0, 0);
    add_ln_kernel<<<SS, 256>>>(y2, tmp, g3, be3, out, nullptr);
}